// round 8
// baseline (speedup 1.0000x reference)
#include <cuda_runtime.h>
#include <cuda_fp16.h>
#include <cstdint>

// ---------------------------------------------------------------------------
// GCNEncoder: 2-layer GCN, N=100000, E=3200000, 128 -> 32 -> 16.
//
// R7: scatter is RED-OP-throughput bound (LTS ~1 RED/partition/cyc,
// payload-width independent: R6 halved bytes, same REDs, got SLOWER).
// => reduce RED count: sort edges by target col (CSR rank is free from the
// histogram atomic; fill is non-atomic), scatter edge-parallel, and
// pre-combine same-col runs with a segmented shfl tree so only run leaders
// issue REDs (avg run = 32 -> ~6x fewer REDs layer1, ~20x layer2).
// fp16 feature tables halve the gather bytes (now the new cap).
// ---------------------------------------------------------------------------

#define N_NODES 100000
#define N_EDGES 3200000
#define IN_C    128
#define HID     32
#define OUT_C   16

#define GEMM_BLOCKS (N_NODES / 32)    // 3125
#define EDGE_BLOCKS (N_EDGES / 256)   // 12500 (exact)

// Scratch (no cudaMalloc allowed) ------------------------------------------
__device__ int    g_degi[N_NODES];
__device__ int    g_off [N_NODES + 1];
__device__ int    g_rowA[N_EDGES];
__device__ int    g_colA[N_EDGES];
__device__ int    g_rank[N_EDGES];         // CSR slot, free from histogram
__device__ int2   g_ecsr[N_EDGES];         // sorted by col: (src, col)
__device__ float  g_dinv[N_NODES];
__device__ __half g_g1h[N_NODES * HID];    // dinv*(x@W1), fp16
__device__ float  g_acc1[N_NODES * HID];
__device__ __half g_g2h[N_NODES * OUT_C];  // dinv*(relu(...)@W2), fp16
__device__ float  g_acc2[N_NODES * OUT_C];
__device__ int    g_is64;

__device__ __forceinline__ int edge_row(const void* ei, int e, int is64) {
    return is64 ? (int)((const long long*)ei)[e] : ((const int*)ei)[e];
}
__device__ __forceinline__ int edge_col(const void* ei, int e, int is64) {
    return is64 ? (int)((const long long*)ei)[(size_t)N_EDGES + e]
                : ((const int*)ei)[(size_t)N_EDGES + e];
}

// K0: dtype detection.
__global__ void k_detect(const void* __restrict__ ei) {
    __shared__ int bad;
    if (threadIdx.x == 0) bad = 0;
    __syncthreads();
    const long long* p = (const long long*)ei;
    for (int i = threadIdx.x; i < 2048; i += blockDim.x) {
        long long v = p[i];
        if (v < 0 || v >= N_NODES) atomicOr(&bad, 1);
    }
    __syncthreads();
    if (threadIdx.x == 0) g_is64 = (bad == 0) ? 1 : 0;
}

// K1 (fused): GEMM blocks write g1h = fp16(x@W1) (unscaled);
// edge blocks decode + histogram + capture CSR rank.
__global__ __launch_bounds__(256) void k_fusedA(const float* __restrict__ x,
                                                const float* __restrict__ W1,
                                                const void*  __restrict__ ei) {
    int tid = threadIdx.x;
    if (blockIdx.x >= GEMM_BLOCKS) {
        int e = (blockIdx.x - GEMM_BLOCKS) * 256 + tid;
        int is64 = g_is64;
        int r = edge_row(ei, e, is64);
        int c = edge_col(ei, e, is64);
        g_rowA[e] = r;
        g_colA[e] = c;
        g_rank[e] = atomicAdd(&g_degi[c], 1);
        return;
    }
    __shared__ float sW[IN_C * HID];
    __shared__ float sx[32][IN_C];
#pragma unroll
    for (int i = tid; i < (IN_C * HID) / 4; i += 256)
        ((float4*)sW)[i] = ((const float4*)W1)[i];

    int nb = blockIdx.x * 32;
#pragma unroll
    for (int i = tid; i < 32 * (IN_C / 4); i += 256) {
        int row = i >> 5, c4 = i & 31;
        ((float4*)sx[row])[c4] =
            ((const float4*)(x + (size_t)(nb + row) * IN_C))[c4];
    }
    __syncthreads();

    int warp = tid >> 5, lane = tid & 31;
    int n0 = warp * 4;
    float a0 = 0.f, a1 = 0.f, a2 = 0.f, a3 = 0.f;
#pragma unroll 4
    for (int kk = 0; kk < IN_C; kk += 4) {
        float4 xa = *(const float4*)&sx[n0 + 0][kk];
        float4 xb = *(const float4*)&sx[n0 + 1][kk];
        float4 xc = *(const float4*)&sx[n0 + 2][kk];
        float4 xd = *(const float4*)&sx[n0 + 3][kk];
        float w0 = sW[(kk + 0) * HID + lane];
        float w1 = sW[(kk + 1) * HID + lane];
        float w2 = sW[(kk + 2) * HID + lane];
        float w3 = sW[(kk + 3) * HID + lane];
        a0 = fmaf(xa.x, w0, fmaf(xa.y, w1, fmaf(xa.z, w2, fmaf(xa.w, w3, a0))));
        a1 = fmaf(xb.x, w0, fmaf(xb.y, w1, fmaf(xb.z, w2, fmaf(xb.w, w3, a1))));
        a2 = fmaf(xc.x, w0, fmaf(xc.y, w1, fmaf(xc.z, w2, fmaf(xc.w, w3, a2))));
        a3 = fmaf(xd.x, w0, fmaf(xd.y, w1, fmaf(xd.z, w2, fmaf(xd.w, w3, a3))));
    }
    g_g1h[(size_t)(nb + n0 + 0) * HID + lane] = __float2half(a0);
    g_g1h[(size_t)(nb + n0 + 1) * HID + lane] = __float2half(a1);
    g_g1h[(size_t)(nb + n0 + 2) * HID + lane] = __float2half(a2);
    g_g1h[(size_t)(nb + n0 + 3) * HID + lane] = __float2half(a3);
}

// K2: single-block scan -> CSR offsets + dinv.
__global__ __launch_bounds__(1024) void k_scan() {
    __shared__ int ssum[1024];
    const int CH = (N_NODES + 1023) / 1024;
    int t = threadIdx.x;
    int begin = t * CH;
    int end   = begin + CH; if (end > N_NODES) end = N_NODES;
    if (begin > N_NODES) begin = N_NODES;
    int s = 0;
    for (int i = begin; i < end; i++) s += g_degi[i];
    ssum[t] = s;
    __syncthreads();
    for (int off = 1; off < 1024; off <<= 1) {
        int v = (t >= off) ? ssum[t - off] : 0;
        __syncthreads();
        ssum[t] += v;
        __syncthreads();
    }
    int run = (t == 0) ? 0 : ssum[t - 1];
    for (int i = begin; i < end; i++) {
        int d = g_degi[i];
        g_off[i]  = run;
        g_dinv[i] = (d > 0) ? rsqrtf((float)d) : 0.0f;
        run += d;
    }
    if (t == 1023) g_off[N_NODES] = run;
}

// K3 (fused): blocks [0,EDGE_BLOCKS) non-atomic sorted fill of (src,col);
// remaining blocks scale g1h by dinv in place (8 halves/thread).
#define SCALE_THREADS (N_NODES * HID / 8)   // 400000
__global__ __launch_bounds__(256) void k_fusedC() {
    int tid = threadIdx.x;
    if (blockIdx.x < EDGE_BLOCKS) {
        int e = blockIdx.x * 256 + tid;
        int c = g_colA[e];
        g_ecsr[g_off[c] + g_rank[e]] = make_int2(g_rowA[e], c);
        return;
    }
    int i = (blockIdx.x - EDGE_BLOCKS) * 256 + tid;   // one uint4 = 8 halves
    if (i >= SCALE_THREADS) return;
    float dv = g_dinv[i >> 2];                        // 4 uint4 per node row
    uint4 p = ((const uint4*)g_g1h)[i];
    __half2* h = (__half2*)&p;
#pragma unroll
    for (int k = 0; k < 4; k++) {
        float2 f = __half22float2(h[k]);
        h[k] = __floats2half2_rn(f.x * dv, f.y * dv);
    }
    ((uint4*)g_g1h)[i] = p;
}

// K4: layer-1 sorted scatter. 4 thr/edge (8 feats), warp = 8 edges x 4
// quarters. Segmented shfl tree combines same-col runs; leaders RED.
__global__ __launch_bounds__(256) void k_scat1s() {
    int t = blockIdx.x * 256 + threadIdx.x;      // grid exact: E*4
    int lane = threadIdx.x & 31;
    int j = lane & 7, q = lane >> 3;
    int e = (t >> 5) * 8 + j;
    int2 rc = g_ecsr[e];
    int r = rc.x, c = rc.y;

    uint4 p = *(const uint4*)(g_g1h + (size_t)r * HID + q * 8);
    float2 f0 = __half22float2(*(__half2*)&p.x);
    float2 f1 = __half22float2(*(__half2*)&p.y);
    float2 f2 = __half22float2(*(__half2*)&p.z);
    float2 f3 = __half22float2(*(__half2*)&p.w);
    float f[8] = {f0.x, f0.y, f1.x, f1.y, f2.x, f2.y, f3.x, f3.y};

#pragma unroll
    for (int k = 1; k < 8; k <<= 1) {
        int nc = __shfl_down_sync(0xffffffffu, c, k);
        bool pred = (j + k < 8) && (nc == c);
        float g[8];
#pragma unroll
        for (int i = 0; i < 8; i++) g[i] = __shfl_down_sync(0xffffffffu, f[i], k);
        if (pred) {
#pragma unroll
            for (int i = 0; i < 8; i++) f[i] += g[i];
        }
    }
    int pc = __shfl_up_sync(0xffffffffu, c, 1);
    bool leader = (j == 0) || (pc != c);
    if (leader) {
        float* dst = g_acc1 + (size_t)c * HID + q * 8;
        asm volatile("red.global.add.v4.f32 [%0], {%1,%2,%3,%4};"
                     :: "l"(dst), "f"(f[0]), "f"(f[1]), "f"(f[2]), "f"(f[3]) : "memory");
        asm volatile("red.global.add.v4.f32 [%0], {%1,%2,%3,%4};"
                     :: "l"(dst + 4), "f"(f[4]), "f"(f[5]), "f"(f[6]), "f"(f[7]) : "memory");
    }
}

// K5: h = relu(acc1*dinv + b1); g2h = fp16(dinv * (h @ W2)). Warp per node.
__global__ __launch_bounds__(256) void k_fuse(const float* __restrict__ W2,
                                              const float* __restrict__ b1) {
    __shared__ float sW[HID * OUT_C];
    __shared__ float sb1[HID];
    __shared__ float sh[8][HID];
    for (int i = threadIdx.x; i < HID * OUT_C; i += 256) sW[i] = W2[i];
    for (int i = threadIdx.x; i < HID; i += 256) sb1[i] = b1[i];
    __syncthreads();

    int warp = threadIdx.x >> 5, lane = threadIdx.x & 31;
    int node = blockIdx.x * 8 + warp;
    if (node >= N_NODES) return;

    float dv = g_dinv[node];
    float h = fmaxf(fmaf(g_acc1[(size_t)node * HID + lane], dv, sb1[lane]), 0.0f);
    sh[warp][lane] = h;
    __syncwarp();

    if (lane < OUT_C) {
        float acc = 0.0f;
#pragma unroll
        for (int k = 0; k < HID; k++)
            acc = fmaf(sh[warp][k], sW[k * OUT_C + lane], acc);
        g_g2h[(size_t)node * OUT_C + lane] = __float2half(acc * dv);
    }
}

// K6: layer-2 sorted scatter. 2 thr/edge, warp = 16 edges x 2 halves.
__global__ __launch_bounds__(256) void k_scat2s() {
    int t = blockIdx.x * 256 + threadIdx.x;      // grid exact: E*2
    int lane = threadIdx.x & 31;
    int j = lane & 15, q = lane >> 4;
    int e = (t >> 5) * 16 + j;
    int2 rc = g_ecsr[e];
    int r = rc.x, c = rc.y;

    uint4 p = *(const uint4*)(g_g2h + (size_t)r * OUT_C + q * 8);
    float2 f0 = __half22float2(*(__half2*)&p.x);
    float2 f1 = __half22float2(*(__half2*)&p.y);
    float2 f2 = __half22float2(*(__half2*)&p.z);
    float2 f3 = __half22float2(*(__half2*)&p.w);
    float f[8] = {f0.x, f0.y, f1.x, f1.y, f2.x, f2.y, f3.x, f3.y};

#pragma unroll
    for (int k = 1; k < 16; k <<= 1) {
        int nc = __shfl_down_sync(0xffffffffu, c, k);
        bool pred = (j + k < 16) && (nc == c);
        float g[8];
#pragma unroll
        for (int i = 0; i < 8; i++) g[i] = __shfl_down_sync(0xffffffffu, f[i], k);
        if (pred) {
#pragma unroll
            for (int i = 0; i < 8; i++) f[i] += g[i];
        }
    }
    int pc = __shfl_up_sync(0xffffffffu, c, 1);
    bool leader = (j == 0) || (pc != c);
    if (leader) {
        float* dst = g_acc2 + (size_t)c * OUT_C + q * 8;
        asm volatile("red.global.add.v4.f32 [%0], {%1,%2,%3,%4};"
                     :: "l"(dst), "f"(f[0]), "f"(f[1]), "f"(f[2]), "f"(f[3]) : "memory");
        asm volatile("red.global.add.v4.f32 [%0], {%1,%2,%3,%4};"
                     :: "l"(dst + 4), "f"(f[4]), "f"(f[5]), "f"(f[6]), "f"(f[7]) : "memory");
    }
}

// K7: out = acc2*dinv + b2; zero-fill tail.
__global__ void k_final(float* __restrict__ out, const float* __restrict__ b2,
                        int out_size) {
    int t = blockIdx.x * blockDim.x + threadIdx.x;
    if (t >= out_size) return;
    if (t < N_NODES * OUT_C) {
        int c = t >> 4, jj = t & 15;
        out[t] = g_acc2[t] * g_dinv[c] + b2[jj];
    } else {
        out[t] = 0.0f;
    }
}

// ---------------------------------------------------------------------------
extern "C" void kernel_launch(void* const* d_in, const int* in_sizes, int n_in,
                              void* d_out, int out_size) {
    const float* x  = (const float*)d_in[0];
    const void*  ei = d_in[1];
    const float* W1 = (const float*)d_in[2];
    const float* b1 = (const float*)d_in[3];
    const float* W2 = (const float*)d_in[4];
    const float* b2 = (const float*)d_in[5];
    float* out = (float*)d_out;

    void *p_degi, *p_acc1, *p_acc2;
    cudaGetSymbolAddress(&p_degi, g_degi);
    cudaGetSymbolAddress(&p_acc1, g_acc1);
    cudaGetSymbolAddress(&p_acc2, g_acc2);
    cudaMemsetAsync(p_degi, 0, (size_t)N_NODES * sizeof(int));
    cudaMemsetAsync(p_acc1, 0, (size_t)N_NODES * HID * sizeof(float));
    cudaMemsetAsync(p_acc2, 0, (size_t)N_NODES * OUT_C * sizeof(float));

    const int scale_blocks = (SCALE_THREADS + 255) / 256;   // 1563
    k_detect<<<1, 256>>>(ei);
    k_fusedA<<<GEMM_BLOCKS + EDGE_BLOCKS, 256>>>(x, W1, ei);
    k_scan  <<<1, 1024>>>();
    k_fusedC<<<EDGE_BLOCKS + scale_blocks, 256>>>();
    k_scat1s<<<(N_EDGES * 4) / 256, 256>>>();
    k_fuse  <<<(N_NODES + 7) / 8, 256>>>(W2, b1);
    k_scat2s<<<(N_EDGES * 2) / 256, 256>>>();
    k_final <<<(out_size + 255) / 256, 256>>>(out, b2, out_size);
}

// round 9
// speedup vs baseline: 1.0004x; 1.0004x over previous
#include <cuda_runtime.h>
#include <cuda_fp16.h>
#include <cstdint>

// ---------------------------------------------------------------------------
// GCNEncoder: 2-layer GCN, N=100000, E=3200000, 128 -> 32 -> 16.
//
// R7: scatter is RED-OP-throughput bound (LTS ~1 RED/partition/cyc,
// payload-width independent: R6 halved bytes, same REDs, got SLOWER).
// => reduce RED count: sort edges by target col (CSR rank is free from the
// histogram atomic; fill is non-atomic), scatter edge-parallel, and
// pre-combine same-col runs with a segmented shfl tree so only run leaders
// issue REDs (avg run = 32 -> ~6x fewer REDs layer1, ~20x layer2).
// fp16 feature tables halve the gather bytes (now the new cap).
// ---------------------------------------------------------------------------

#define N_NODES 100000
#define N_EDGES 3200000
#define IN_C    128
#define HID     32
#define OUT_C   16

#define GEMM_BLOCKS (N_NODES / 32)    // 3125
#define EDGE_BLOCKS (N_EDGES / 256)   // 12500 (exact)

// Scratch (no cudaMalloc allowed) ------------------------------------------
__device__ int    g_degi[N_NODES];
__device__ int    g_off [N_NODES + 1];
__device__ int    g_rowA[N_EDGES];
__device__ int    g_colA[N_EDGES];
__device__ int    g_rank[N_EDGES];         // CSR slot, free from histogram
__device__ int2   g_ecsr[N_EDGES];         // sorted by col: (src, col)
__device__ float  g_dinv[N_NODES];
__device__ __half g_g1h[N_NODES * HID];    // dinv*(x@W1), fp16
__device__ float  g_acc1[N_NODES * HID];
__device__ __half g_g2h[N_NODES * OUT_C];  // dinv*(relu(...)@W2), fp16
__device__ float  g_acc2[N_NODES * OUT_C];
__device__ int    g_is64;

__device__ __forceinline__ int edge_row(const void* ei, int e, int is64) {
    return is64 ? (int)((const long long*)ei)[e] : ((const int*)ei)[e];
}
__device__ __forceinline__ int edge_col(const void* ei, int e, int is64) {
    return is64 ? (int)((const long long*)ei)[(size_t)N_EDGES + e]
                : ((const int*)ei)[(size_t)N_EDGES + e];
}

// K0: dtype detection.
__global__ void k_detect(const void* __restrict__ ei) {
    __shared__ int bad;
    if (threadIdx.x == 0) bad = 0;
    __syncthreads();
    const long long* p = (const long long*)ei;
    for (int i = threadIdx.x; i < 2048; i += blockDim.x) {
        long long v = p[i];
        if (v < 0 || v >= N_NODES) atomicOr(&bad, 1);
    }
    __syncthreads();
    if (threadIdx.x == 0) g_is64 = (bad == 0) ? 1 : 0;
}

// K1 (fused): GEMM blocks write g1h = fp16(x@W1) (unscaled);
// edge blocks decode + histogram + capture CSR rank.
__global__ __launch_bounds__(256) void k_fusedA(const float* __restrict__ x,
                                                const float* __restrict__ W1,
                                                const void*  __restrict__ ei) {
    int tid = threadIdx.x;
    if (blockIdx.x >= GEMM_BLOCKS) {
        int e = (blockIdx.x - GEMM_BLOCKS) * 256 + tid;
        int is64 = g_is64;
        int r = edge_row(ei, e, is64);
        int c = edge_col(ei, e, is64);
        g_rowA[e] = r;
        g_colA[e] = c;
        g_rank[e] = atomicAdd(&g_degi[c], 1);
        return;
    }
    __shared__ float sW[IN_C * HID];
    __shared__ float sx[32][IN_C];
#pragma unroll
    for (int i = tid; i < (IN_C * HID) / 4; i += 256)
        ((float4*)sW)[i] = ((const float4*)W1)[i];

    int nb = blockIdx.x * 32;
#pragma unroll
    for (int i = tid; i < 32 * (IN_C / 4); i += 256) {
        int row = i >> 5, c4 = i & 31;
        ((float4*)sx[row])[c4] =
            ((const float4*)(x + (size_t)(nb + row) * IN_C))[c4];
    }
    __syncthreads();

    int warp = tid >> 5, lane = tid & 31;
    int n0 = warp * 4;
    float a0 = 0.f, a1 = 0.f, a2 = 0.f, a3 = 0.f;
#pragma unroll 4
    for (int kk = 0; kk < IN_C; kk += 4) {
        float4 xa = *(const float4*)&sx[n0 + 0][kk];
        float4 xb = *(const float4*)&sx[n0 + 1][kk];
        float4 xc = *(const float4*)&sx[n0 + 2][kk];
        float4 xd = *(const float4*)&sx[n0 + 3][kk];
        float w0 = sW[(kk + 0) * HID + lane];
        float w1 = sW[(kk + 1) * HID + lane];
        float w2 = sW[(kk + 2) * HID + lane];
        float w3 = sW[(kk + 3) * HID + lane];
        a0 = fmaf(xa.x, w0, fmaf(xa.y, w1, fmaf(xa.z, w2, fmaf(xa.w, w3, a0))));
        a1 = fmaf(xb.x, w0, fmaf(xb.y, w1, fmaf(xb.z, w2, fmaf(xb.w, w3, a1))));
        a2 = fmaf(xc.x, w0, fmaf(xc.y, w1, fmaf(xc.z, w2, fmaf(xc.w, w3, a2))));
        a3 = fmaf(xd.x, w0, fmaf(xd.y, w1, fmaf(xd.z, w2, fmaf(xd.w, w3, a3))));
    }
    g_g1h[(size_t)(nb + n0 + 0) * HID + lane] = __float2half(a0);
    g_g1h[(size_t)(nb + n0 + 1) * HID + lane] = __float2half(a1);
    g_g1h[(size_t)(nb + n0 + 2) * HID + lane] = __float2half(a2);
    g_g1h[(size_t)(nb + n0 + 3) * HID + lane] = __float2half(a3);
}

// K2: single-block scan -> CSR offsets + dinv.
__global__ __launch_bounds__(1024) void k_scan() {
    __shared__ int ssum[1024];
    const int CH = (N_NODES + 1023) / 1024;
    int t = threadIdx.x;
    int begin = t * CH;
    int end   = begin + CH; if (end > N_NODES) end = N_NODES;
    if (begin > N_NODES) begin = N_NODES;
    int s = 0;
    for (int i = begin; i < end; i++) s += g_degi[i];
    ssum[t] = s;
    __syncthreads();
    for (int off = 1; off < 1024; off <<= 1) {
        int v = (t >= off) ? ssum[t - off] : 0;
        __syncthreads();
        ssum[t] += v;
        __syncthreads();
    }
    int run = (t == 0) ? 0 : ssum[t - 1];
    for (int i = begin; i < end; i++) {
        int d = g_degi[i];
        g_off[i]  = run;
        g_dinv[i] = (d > 0) ? rsqrtf((float)d) : 0.0f;
        run += d;
    }
    if (t == 1023) g_off[N_NODES] = run;
}

// K3 (fused): blocks [0,EDGE_BLOCKS) non-atomic sorted fill of (src,col);
// remaining blocks scale g1h by dinv in place (8 halves/thread).
#define SCALE_THREADS (N_NODES * HID / 8)   // 400000
__global__ __launch_bounds__(256) void k_fusedC() {
    int tid = threadIdx.x;
    if (blockIdx.x < EDGE_BLOCKS) {
        int e = blockIdx.x * 256 + tid;
        int c = g_colA[e];
        g_ecsr[g_off[c] + g_rank[e]] = make_int2(g_rowA[e], c);
        return;
    }
    int i = (blockIdx.x - EDGE_BLOCKS) * 256 + tid;   // one uint4 = 8 halves
    if (i >= SCALE_THREADS) return;
    float dv = g_dinv[i >> 2];                        // 4 uint4 per node row
    uint4 p = ((const uint4*)g_g1h)[i];
    __half2* h = (__half2*)&p;
#pragma unroll
    for (int k = 0; k < 4; k++) {
        float2 f = __half22float2(h[k]);
        h[k] = __floats2half2_rn(f.x * dv, f.y * dv);
    }
    ((uint4*)g_g1h)[i] = p;
}

// K4: layer-1 sorted scatter. 4 thr/edge (8 feats), warp = 8 edges x 4
// quarters. Segmented shfl tree combines same-col runs; leaders RED.
__global__ __launch_bounds__(256) void k_scat1s() {
    int t = blockIdx.x * 256 + threadIdx.x;      // grid exact: E*4
    int lane = threadIdx.x & 31;
    int j = lane & 7, q = lane >> 3;
    int e = (t >> 5) * 8 + j;
    int2 rc = g_ecsr[e];
    int r = rc.x, c = rc.y;

    uint4 p = *(const uint4*)(g_g1h + (size_t)r * HID + q * 8);
    float2 f0 = __half22float2(*(__half2*)&p.x);
    float2 f1 = __half22float2(*(__half2*)&p.y);
    float2 f2 = __half22float2(*(__half2*)&p.z);
    float2 f3 = __half22float2(*(__half2*)&p.w);
    float f[8] = {f0.x, f0.y, f1.x, f1.y, f2.x, f2.y, f3.x, f3.y};

#pragma unroll
    for (int k = 1; k < 8; k <<= 1) {
        int nc = __shfl_down_sync(0xffffffffu, c, k);
        bool pred = (j + k < 8) && (nc == c);
        float g[8];
#pragma unroll
        for (int i = 0; i < 8; i++) g[i] = __shfl_down_sync(0xffffffffu, f[i], k);
        if (pred) {
#pragma unroll
            for (int i = 0; i < 8; i++) f[i] += g[i];
        }
    }
    int pc = __shfl_up_sync(0xffffffffu, c, 1);
    bool leader = (j == 0) || (pc != c);
    if (leader) {
        float* dst = g_acc1 + (size_t)c * HID + q * 8;
        asm volatile("red.global.add.v4.f32 [%0], {%1,%2,%3,%4};"
                     :: "l"(dst), "f"(f[0]), "f"(f[1]), "f"(f[2]), "f"(f[3]) : "memory");
        asm volatile("red.global.add.v4.f32 [%0], {%1,%2,%3,%4};"
                     :: "l"(dst + 4), "f"(f[4]), "f"(f[5]), "f"(f[6]), "f"(f[7]) : "memory");
    }
}

// K5: h = relu(acc1*dinv + b1); g2h = fp16(dinv * (h @ W2)). Warp per node.
__global__ __launch_bounds__(256) void k_fuse(const float* __restrict__ W2,
                                              const float* __restrict__ b1) {
    __shared__ float sW[HID * OUT_C];
    __shared__ float sb1[HID];
    __shared__ float sh[8][HID];
    for (int i = threadIdx.x; i < HID * OUT_C; i += 256) sW[i] = W2[i];
    for (int i = threadIdx.x; i < HID; i += 256) sb1[i] = b1[i];
    __syncthreads();

    int warp = threadIdx.x >> 5, lane = threadIdx.x & 31;
    int node = blockIdx.x * 8 + warp;
    if (node >= N_NODES) return;

    float dv = g_dinv[node];
    float h = fmaxf(fmaf(g_acc1[(size_t)node * HID + lane], dv, sb1[lane]), 0.0f);
    sh[warp][lane] = h;
    __syncwarp();

    if (lane < OUT_C) {
        float acc = 0.0f;
#pragma unroll
        for (int k = 0; k < HID; k++)
            acc = fmaf(sh[warp][k], sW[k * OUT_C + lane], acc);
        g_g2h[(size_t)node * OUT_C + lane] = __float2half(acc * dv);
    }
}

// K6: layer-2 sorted scatter. 2 thr/edge, warp = 16 edges x 2 halves.
__global__ __launch_bounds__(256) void k_scat2s() {
    int t = blockIdx.x * 256 + threadIdx.x;      // grid exact: E*2
    int lane = threadIdx.x & 31;
    int j = lane & 15, q = lane >> 4;
    int e = (t >> 5) * 16 + j;
    int2 rc = g_ecsr[e];
    int r = rc.x, c = rc.y;

    uint4 p = *(const uint4*)(g_g2h + (size_t)r * OUT_C + q * 8);
    float2 f0 = __half22float2(*(__half2*)&p.x);
    float2 f1 = __half22float2(*(__half2*)&p.y);
    float2 f2 = __half22float2(*(__half2*)&p.z);
    float2 f3 = __half22float2(*(__half2*)&p.w);
    float f[8] = {f0.x, f0.y, f1.x, f1.y, f2.x, f2.y, f3.x, f3.y};

#pragma unroll
    for (int k = 1; k < 16; k <<= 1) {
        int nc = __shfl_down_sync(0xffffffffu, c, k);
        bool pred = (j + k < 16) && (nc == c);
        float g[8];
#pragma unroll
        for (int i = 0; i < 8; i++) g[i] = __shfl_down_sync(0xffffffffu, f[i], k);
        if (pred) {
#pragma unroll
            for (int i = 0; i < 8; i++) f[i] += g[i];
        }
    }
    int pc = __shfl_up_sync(0xffffffffu, c, 1);
    bool leader = (j == 0) || (pc != c);
    if (leader) {
        float* dst = g_acc2 + (size_t)c * OUT_C + q * 8;
        asm volatile("red.global.add.v4.f32 [%0], {%1,%2,%3,%4};"
                     :: "l"(dst), "f"(f[0]), "f"(f[1]), "f"(f[2]), "f"(f[3]) : "memory");
        asm volatile("red.global.add.v4.f32 [%0], {%1,%2,%3,%4};"
                     :: "l"(dst + 4), "f"(f[4]), "f"(f[5]), "f"(f[6]), "f"(f[7]) : "memory");
    }
}

// K7: out = acc2*dinv + b2; zero-fill tail.
__global__ void k_final(float* __restrict__ out, const float* __restrict__ b2,
                        int out_size) {
    int t = blockIdx.x * blockDim.x + threadIdx.x;
    if (t >= out_size) return;
    if (t < N_NODES * OUT_C) {
        int c = t >> 4, jj = t & 15;
        out[t] = g_acc2[t] * g_dinv[c] + b2[jj];
    } else {
        out[t] = 0.0f;
    }
}

// ---------------------------------------------------------------------------
extern "C" void kernel_launch(void* const* d_in, const int* in_sizes, int n_in,
                              void* d_out, int out_size) {
    const float* x  = (const float*)d_in[0];
    const void*  ei = d_in[1];
    const float* W1 = (const float*)d_in[2];
    const float* b1 = (const float*)d_in[3];
    const float* W2 = (const float*)d_in[4];
    const float* b2 = (const float*)d_in[5];
    float* out = (float*)d_out;

    void *p_degi, *p_acc1, *p_acc2;
    cudaGetSymbolAddress(&p_degi, g_degi);
    cudaGetSymbolAddress(&p_acc1, g_acc1);
    cudaGetSymbolAddress(&p_acc2, g_acc2);
    cudaMemsetAsync(p_degi, 0, (size_t)N_NODES * sizeof(int));
    cudaMemsetAsync(p_acc1, 0, (size_t)N_NODES * HID * sizeof(float));
    cudaMemsetAsync(p_acc2, 0, (size_t)N_NODES * OUT_C * sizeof(float));

    const int scale_blocks = (SCALE_THREADS + 255) / 256;   // 1563
    k_detect<<<1, 256>>>(ei);
    k_fusedA<<<GEMM_BLOCKS + EDGE_BLOCKS, 256>>>(x, W1, ei);
    k_scan  <<<1, 1024>>>();
    k_fusedC<<<EDGE_BLOCKS + scale_blocks, 256>>>();
    k_scat1s<<<(N_EDGES * 4) / 256, 256>>>();
    k_fuse  <<<(N_NODES + 7) / 8, 256>>>(W2, b1);
    k_scat2s<<<(N_EDGES * 2) / 256, 256>>>();
    k_final <<<(out_size + 255) / 256, 256>>>(out, b2, out_size);
}

// round 10
// speedup vs baseline: 1.2542x; 1.2536x over previous
#include <cuda_runtime.h>
#include <cstdint>

// ---------------------------------------------------------------------------
// GCNEncoder: 2-layer GCN, N=100000, E=3200000, 128 -> 32 -> 16.
//
// R8: scatter is RED-op-rate bound (~1 RED/LTS-partition/cyc; R4's 93us ==
// 25.6M/184 exactly). R7 cut REDs via sort but burned ~320us on SHFLs (MIO
// rt ~8cyc, 11M of them). This round: same sort (rank free from histogram
// atomic, non-atomic fill -- both measured fine in R7), but the same-col
// combine is SERIAL IN-THREAD: each thread owns a float4 chunk of 8
// consecutive sorted edges, 8 independent coalesced gathers, register FADD
// combine, ~1.2 segments -> ~1.2 REDs. No shuffles anywhere.
// Everything else is byte-for-byte R4 (fp32 tables, rel_err ~2e-7).
// ---------------------------------------------------------------------------

#define N_NODES 100000
#define N_EDGES 3200000
#define IN_C    128
#define HID     32
#define OUT_C   16

#define GEMM_BLOCKS  (N_NODES / 32)          // 3125
#define EDGE_BLOCKS  (N_EDGES / 256)         // 12500 (exact)
#define SCALE_BLOCKS (N_NODES * HID / 4 / 256) // 3125 (float4 per thread)

// Scratch (no cudaMalloc allowed) ------------------------------------------
__device__ int    g_degi[N_NODES];
__device__ int    g_off [N_NODES + 1];
__device__ int    g_rowA[N_EDGES];
__device__ int    g_colA[N_EDGES];
__device__ int    g_rank[N_EDGES];            // CSR slot, free from histogram
__device__ __align__(16) int2  g_ecsr[N_EDGES];   // sorted by col: (src, col)
__device__ float  g_dinv[N_NODES];
__device__ __align__(16) float g_g1  [N_NODES * HID];   // dinv*(x@W1)
__device__ __align__(16) float g_acc1[N_NODES * HID];
__device__ __align__(16) float g_g2  [N_NODES * OUT_C]; // dinv*(relu@W2)
__device__ __align__(16) float g_acc2[N_NODES * OUT_C];
__device__ int    g_is64;

__device__ __forceinline__ int edge_row(const void* ei, int e, int is64) {
    return is64 ? (int)((const long long*)ei)[e] : ((const int*)ei)[e];
}
__device__ __forceinline__ int edge_col(const void* ei, int e, int is64) {
    return is64 ? (int)((const long long*)ei)[(size_t)N_EDGES + e]
                : ((const int*)ei)[(size_t)N_EDGES + e];
}

__device__ __forceinline__ void red_v4(float* dst, float4 v) {
    asm volatile("red.global.add.v4.f32 [%0], {%1,%2,%3,%4};"
                 :: "l"(dst), "f"(v.x), "f"(v.y), "f"(v.z), "f"(v.w) : "memory");
}

// K0: dtype detection (int64 view of genuine int32 data leaves [0,N) with
// overwhelming probability across 2048 samples).
__global__ void k_detect(const void* __restrict__ ei) {
    __shared__ int bad;
    if (threadIdx.x == 0) bad = 0;
    __syncthreads();
    const long long* p = (const long long*)ei;
    for (int i = threadIdx.x; i < 2048; i += blockDim.x) {
        long long v = p[i];
        if (v < 0 || v >= N_NODES) atomicOr(&bad, 1);
    }
    __syncthreads();
    if (threadIdx.x == 0) g_is64 = (bad == 0) ? 1 : 0;
}

// K1 (fused): GEMM blocks write g1 = x@W1 (fp32, unscaled);
// edge blocks decode + histogram + capture CSR rank (rank is free).
__global__ __launch_bounds__(256) void k_fusedA(const float* __restrict__ x,
                                                const float* __restrict__ W1,
                                                const void*  __restrict__ ei) {
    int tid = threadIdx.x;
    if (blockIdx.x >= GEMM_BLOCKS) {
        int e = (blockIdx.x - GEMM_BLOCKS) * 256 + tid;
        int is64 = g_is64;
        int r = edge_row(ei, e, is64);
        int c = edge_col(ei, e, is64);
        g_rowA[e] = r;
        g_colA[e] = c;
        g_rank[e] = atomicAdd(&g_degi[c], 1);
        return;
    }
    __shared__ float sW[IN_C * HID];
    __shared__ float sx[32][IN_C];
#pragma unroll
    for (int i = tid; i < (IN_C * HID) / 4; i += 256)
        ((float4*)sW)[i] = ((const float4*)W1)[i];

    int nb = blockIdx.x * 32;
#pragma unroll
    for (int i = tid; i < 32 * (IN_C / 4); i += 256) {
        int row = i >> 5, c4 = i & 31;
        ((float4*)sx[row])[c4] =
            ((const float4*)(x + (size_t)(nb + row) * IN_C))[c4];
    }
    __syncthreads();

    int warp = tid >> 5, lane = tid & 31;
    int n0 = warp * 4;
    float a0 = 0.f, a1 = 0.f, a2 = 0.f, a3 = 0.f;
#pragma unroll 4
    for (int kk = 0; kk < IN_C; kk += 4) {
        float4 xa = *(const float4*)&sx[n0 + 0][kk];
        float4 xb = *(const float4*)&sx[n0 + 1][kk];
        float4 xc = *(const float4*)&sx[n0 + 2][kk];
        float4 xd = *(const float4*)&sx[n0 + 3][kk];
        float w0 = sW[(kk + 0) * HID + lane];
        float w1 = sW[(kk + 1) * HID + lane];
        float w2 = sW[(kk + 2) * HID + lane];
        float w3 = sW[(kk + 3) * HID + lane];
        a0 = fmaf(xa.x, w0, fmaf(xa.y, w1, fmaf(xa.z, w2, fmaf(xa.w, w3, a0))));
        a1 = fmaf(xb.x, w0, fmaf(xb.y, w1, fmaf(xb.z, w2, fmaf(xb.w, w3, a1))));
        a2 = fmaf(xc.x, w0, fmaf(xc.y, w1, fmaf(xc.z, w2, fmaf(xc.w, w3, a2))));
        a3 = fmaf(xd.x, w0, fmaf(xd.y, w1, fmaf(xd.z, w2, fmaf(xd.w, w3, a3))));
    }
    g_g1[(size_t)(nb + n0 + 0) * HID + lane] = a0;
    g_g1[(size_t)(nb + n0 + 1) * HID + lane] = a1;
    g_g1[(size_t)(nb + n0 + 2) * HID + lane] = a2;
    g_g1[(size_t)(nb + n0 + 3) * HID + lane] = a3;
}

// K2: single-block scan -> CSR offsets + dinv.
__global__ __launch_bounds__(1024) void k_scan() {
    __shared__ int ssum[1024];
    const int CH = (N_NODES + 1023) / 1024;
    int t = threadIdx.x;
    int begin = t * CH;
    int end   = begin + CH; if (end > N_NODES) end = N_NODES;
    if (begin > N_NODES) begin = N_NODES;
    int s = 0;
    for (int i = begin; i < end; i++) s += g_degi[i];
    ssum[t] = s;
    __syncthreads();
    for (int off = 1; off < 1024; off <<= 1) {
        int v = (t >= off) ? ssum[t - off] : 0;
        __syncthreads();
        ssum[t] += v;
        __syncthreads();
    }
    int run = (t == 0) ? 0 : ssum[t - 1];
    for (int i = begin; i < end; i++) {
        int d = g_degi[i];
        g_off[i]  = run;
        g_dinv[i] = (d > 0) ? rsqrtf((float)d) : 0.0f;
        run += d;
    }
    if (t == 1023) g_off[N_NODES] = run;
}

// K3 (fused): blocks [0,EDGE_BLOCKS) non-atomic sorted fill of (src,col);
// remaining blocks scale g1 by dinv in place (float4 per thread).
__global__ __launch_bounds__(256) void k_fusedC() {
    int tid = threadIdx.x;
    if (blockIdx.x < EDGE_BLOCKS) {
        int e = blockIdx.x * 256 + tid;
        int c = g_colA[e];
        g_ecsr[g_off[c] + g_rank[e]] = make_int2(g_rowA[e], c);
        return;
    }
    int i = (blockIdx.x - EDGE_BLOCKS) * 256 + tid;  // float4 index
    float dv = g_dinv[i >> 3];                        // 8 float4 per 32-f row
    float4 v = ((const float4*)g_g1)[i];
    v.x *= dv; v.y *= dv; v.z *= dv; v.w *= dv;
    ((float4*)g_g1)[i] = v;
}

// K4: layer-1 sorted scatter, serial in-thread combine.
// Thread = one float4 chunk (q in 0..7) of 8 consecutive sorted edges.
// Lanes 0..7 of an octet jointly read full 128B g1 rows (coalesced).
// ~1.2 segments per 8 edges -> ~1.2 REDs/thread (was 8/edge in R4).
__global__ __launch_bounds__(256) void k_scat1() {
    int t = blockIdx.x * 256 + threadIdx.x;   // 3.2M threads
    int q   = t & 7;                          // float4 chunk of the 32-f row
    int oct = t >> 3;                         // edge octet
    int e0  = oct * 8;

    const int4* em = (const int4*)(g_ecsr + e0);   // 8 int2 = 4 int4
    int4 m0 = em[0], m1 = em[1], m2 = em[2], m3 = em[3];
    int src[8] = {m0.x, m0.z, m1.x, m1.z, m2.x, m2.z, m3.x, m3.z};
    int col[8] = {m0.y, m0.w, m1.y, m1.w, m2.y, m2.w, m3.y, m3.w};

    float4 v[8];
#pragma unroll
    for (int k = 0; k < 8; k++)
        v[k] = *(const float4*)(g_g1 + (size_t)src[k] * HID + q * 4);

    float4 acc = v[0];
    int cur = col[0];
#pragma unroll
    for (int k = 1; k < 8; k++) {
        if (col[k] == cur) {
            acc.x += v[k].x; acc.y += v[k].y; acc.z += v[k].z; acc.w += v[k].w;
        } else {
            red_v4(g_acc1 + (size_t)cur * HID + q * 4, acc);
            acc = v[k]; cur = col[k];
        }
    }
    red_v4(g_acc1 + (size_t)cur * HID + q * 4, acc);
}

// K5: h = relu(acc1*dinv + b1); g2 = dinv * (h @ W2). Warp per node.
__global__ __launch_bounds__(256) void k_fuse(const float* __restrict__ W2,
                                              const float* __restrict__ b1) {
    __shared__ float sW[HID * OUT_C];
    __shared__ float sb1[HID];
    __shared__ float sh[8][HID];
    for (int i = threadIdx.x; i < HID * OUT_C; i += 256) sW[i] = W2[i];
    for (int i = threadIdx.x; i < HID; i += 256) sb1[i] = b1[i];
    __syncthreads();

    int warp = threadIdx.x >> 5, lane = threadIdx.x & 31;
    int node = blockIdx.x * 8 + warp;
    if (node >= N_NODES) return;

    float dv = g_dinv[node];
    float h = fmaxf(fmaf(g_acc1[(size_t)node * HID + lane], dv, sb1[lane]), 0.0f);
    sh[warp][lane] = h;
    __syncwarp();

    if (lane < OUT_C) {
        float acc = 0.0f;
#pragma unroll
        for (int k = 0; k < HID; k++)
            acc = fmaf(sh[warp][k], sW[k * OUT_C + lane], acc);
        g_g2[(size_t)node * OUT_C + lane] = acc * dv;
    }
}

// K6: layer-2 sorted scatter, same scheme. Thread = float4 chunk (q in 0..3)
// of 8 consecutive sorted edges; 4 lanes cover a 64B g2 row.
__global__ __launch_bounds__(256) void k_scat2() {
    int t = blockIdx.x * 256 + threadIdx.x;   // 1.6M threads
    int q   = t & 3;
    int oct = t >> 2;
    int e0  = oct * 8;

    const int4* em = (const int4*)(g_ecsr + e0);
    int4 m0 = em[0], m1 = em[1], m2 = em[2], m3 = em[3];
    int src[8] = {m0.x, m0.z, m1.x, m1.z, m2.x, m2.z, m3.x, m3.z};
    int col[8] = {m0.y, m0.w, m1.y, m1.w, m2.y, m2.w, m3.y, m3.w};

    float4 v[8];
#pragma unroll
    for (int k = 0; k < 8; k++)
        v[k] = *(const float4*)(g_g2 + (size_t)src[k] * OUT_C + q * 4);

    float4 acc = v[0];
    int cur = col[0];
#pragma unroll
    for (int k = 1; k < 8; k++) {
        if (col[k] == cur) {
            acc.x += v[k].x; acc.y += v[k].y; acc.z += v[k].z; acc.w += v[k].w;
        } else {
            red_v4(g_acc2 + (size_t)cur * OUT_C + q * 4, acc);
            acc = v[k]; cur = col[k];
        }
    }
    red_v4(g_acc2 + (size_t)cur * OUT_C + q * 4, acc);
}

// K7: out = acc2*dinv + b2; zero-fill tail (tuple scalar slot).
__global__ void k_final(float* __restrict__ out, const float* __restrict__ b2,
                        int out_size) {
    int t = blockIdx.x * blockDim.x + threadIdx.x;
    if (t >= out_size) return;
    if (t < N_NODES * OUT_C) {
        int c = t >> 4, j = t & 15;
        out[t] = g_acc2[t] * g_dinv[c] + b2[j];
    } else {
        out[t] = 0.0f;
    }
}

// ---------------------------------------------------------------------------
extern "C" void kernel_launch(void* const* d_in, const int* in_sizes, int n_in,
                              void* d_out, int out_size) {
    const float* x  = (const float*)d_in[0];
    const void*  ei = d_in[1];
    const float* W1 = (const float*)d_in[2];
    const float* b1 = (const float*)d_in[3];
    const float* W2 = (const float*)d_in[4];
    const float* b2 = (const float*)d_in[5];
    float* out = (float*)d_out;

    void *p_degi, *p_acc1, *p_acc2;
    cudaGetSymbolAddress(&p_degi, g_degi);
    cudaGetSymbolAddress(&p_acc1, g_acc1);
    cudaGetSymbolAddress(&p_acc2, g_acc2);
    cudaMemsetAsync(p_degi, 0, (size_t)N_NODES * sizeof(int));
    cudaMemsetAsync(p_acc1, 0, (size_t)N_NODES * HID * sizeof(float));
    cudaMemsetAsync(p_acc2, 0, (size_t)N_NODES * OUT_C * sizeof(float));

    k_detect<<<1, 256>>>(ei);
    k_fusedA<<<GEMM_BLOCKS + EDGE_BLOCKS, 256>>>(x, W1, ei);
    k_scan  <<<1, 1024>>>();
    k_fusedC<<<EDGE_BLOCKS + SCALE_BLOCKS, 256>>>();
    k_scat1 <<<(N_EDGES * 8 / 8) / 256, 256>>>();   // 3.2M threads, 12500 blocks
    k_fuse  <<<(N_NODES + 7) / 8, 256>>>(W2, b1);
    k_scat2 <<<(N_EDGES * 4 / 8) / 256, 256>>>();   // 1.6M threads, 6250 blocks
    k_final <<<(out_size + 255) / 256, 256>>>(out, b2, out_size);
}

// round 11
// speedup vs baseline: 2.1600x; 1.7222x over previous
#include <cuda_runtime.h>
#include <cuda_fp16.h>
#include <cstdint>

// ---------------------------------------------------------------------------
// GCNEncoder: 2-layer GCN, N=100000, E=3200000, 128 -> 32 -> 16.
//
// R10 = R4 (best, 234us) + fp16 layer-1 accumulator.
// Scatter cost model (validated): each RED lane hits a random 128B line ->
// one L1tex wavefront per lane; cost = lane count, payload-width independent
// (R4 scat1 93us == 25.6M lanes/148 SMs). fp16 accumulator packs 8 feats
// per 16B lane via red.global.add.noftz.v4.f16x2 -> 4 lanes/edge (was 8)
// -> scat1 ~47us. Gathers stay fp32+coalesced; layer-2 accum stays fp32.
// Sorted/CSR designs failed 4x (R3/R5/R7/R8): infra + metadata costs exceed
// RED savings. Do not revisit.
// ---------------------------------------------------------------------------

#define N_NODES 100000
#define N_EDGES 3200000
#define IN_C    128
#define HID     32
#define OUT_C   16

#define GEMM_BLOCKS (N_NODES / 32)    // 3125
#define EDGE_BLOCKS (N_EDGES / 256)   // 12500 (exact)

// Scratch (no cudaMalloc allowed) ------------------------------------------
__device__ int    g_degi[N_NODES];
__device__ int    g_row [N_EDGES];
__device__ int    g_col [N_EDGES];
__device__ float  g_dinv[N_NODES];
__device__ __align__(16) float  g_g1  [N_NODES * HID];   // dinv*(x@W1)
__device__ __align__(16) __half g_acc1[N_NODES * HID];   // fp16 accumulator
__device__ __align__(16) float  g_g2  [N_NODES * OUT_C]; // dinv*(relu@W2)
__device__ __align__(16) float  g_acc2[N_NODES * OUT_C]; // fp32 accumulator
__device__ int    g_is64;

__device__ __forceinline__ int edge_row(const void* ei, int e, int is64) {
    return is64 ? (int)((const long long*)ei)[e] : ((const int*)ei)[e];
}
__device__ __forceinline__ int edge_col(const void* ei, int e, int is64) {
    return is64 ? (int)((const long long*)ei)[(size_t)N_EDGES + e]
                : ((const int*)ei)[(size_t)N_EDGES + e];
}

// K0: dtype detection (int64 view of genuine int32 data leaves [0,N) with
// overwhelming probability across 2048 samples).
__global__ void k_detect(const void* __restrict__ ei) {
    __shared__ int bad;
    if (threadIdx.x == 0) bad = 0;
    __syncthreads();
    const long long* p = (const long long*)ei;
    for (int i = threadIdx.x; i < 2048; i += blockDim.x) {
        long long v = p[i];
        if (v < 0 || v >= N_NODES) atomicOr(&bad, 1);
    }
    __syncthreads();
    if (threadIdx.x == 0) g_is64 = (bad == 0) ? 1 : 0;
}

// K1 (fused): blocks [0,GEMM_BLOCKS) register-tiled g1 = x@W1 (unscaled);
// blocks [GEMM_BLOCKS,+EDGE_BLOCKS) decode indices + degree histogram.
__global__ __launch_bounds__(256) void k_fusedA(const float* __restrict__ x,
                                                const float* __restrict__ W1,
                                                const void*  __restrict__ ei) {
    int tid = threadIdx.x;
    if (blockIdx.x >= GEMM_BLOCKS) {
        int e = (blockIdx.x - GEMM_BLOCKS) * 256 + tid;
        int is64 = g_is64;
        int r = edge_row(ei, e, is64);
        int c = edge_col(ei, e, is64);
        g_row[e] = r;
        g_col[e] = c;
        atomicAdd(&g_degi[c], 1);
        return;
    }
    __shared__ float sW[IN_C * HID];
    __shared__ float sx[32][IN_C];
#pragma unroll
    for (int i = tid; i < (IN_C * HID) / 4; i += 256)
        ((float4*)sW)[i] = ((const float4*)W1)[i];

    int nb = blockIdx.x * 32;
#pragma unroll
    for (int i = tid; i < 32 * (IN_C / 4); i += 256) {
        int row = i >> 5, c4 = i & 31;
        ((float4*)sx[row])[c4] =
            ((const float4*)(x + (size_t)(nb + row) * IN_C))[c4];
    }
    __syncthreads();

    int warp = tid >> 5, lane = tid & 31;
    int n0 = warp * 4;
    float a0 = 0.f, a1 = 0.f, a2 = 0.f, a3 = 0.f;
#pragma unroll 4
    for (int kk = 0; kk < IN_C; kk += 4) {
        float4 xa = *(const float4*)&sx[n0 + 0][kk];
        float4 xb = *(const float4*)&sx[n0 + 1][kk];
        float4 xc = *(const float4*)&sx[n0 + 2][kk];
        float4 xd = *(const float4*)&sx[n0 + 3][kk];
        float w0 = sW[(kk + 0) * HID + lane];
        float w1 = sW[(kk + 1) * HID + lane];
        float w2 = sW[(kk + 2) * HID + lane];
        float w3 = sW[(kk + 3) * HID + lane];
        a0 = fmaf(xa.x, w0, fmaf(xa.y, w1, fmaf(xa.z, w2, fmaf(xa.w, w3, a0))));
        a1 = fmaf(xb.x, w0, fmaf(xb.y, w1, fmaf(xb.z, w2, fmaf(xb.w, w3, a1))));
        a2 = fmaf(xc.x, w0, fmaf(xc.y, w1, fmaf(xc.z, w2, fmaf(xc.w, w3, a2))));
        a3 = fmaf(xd.x, w0, fmaf(xd.y, w1, fmaf(xd.z, w2, fmaf(xd.w, w3, a3))));
    }
    g_g1[(size_t)(nb + n0 + 0) * HID + lane] = a0;
    g_g1[(size_t)(nb + n0 + 1) * HID + lane] = a1;
    g_g1[(size_t)(nb + n0 + 2) * HID + lane] = a2;
    g_g1[(size_t)(nb + n0 + 3) * HID + lane] = a3;
}

// K2: dinv = rsqrt(deg) (or 0); scale g1 rows in place.
__global__ void k_scale() {
    int t = blockIdx.x * blockDim.x + threadIdx.x;
    if (t >= N_NODES * HID) return;
    int node = t >> 5;                      // HID == 32
    int d = g_degi[node];                   // warp-broadcast
    float dv = (d > 0) ? rsqrtf((float)d) : 0.0f;
    g_g1[t] *= dv;
    if ((t & 31) == 0) g_dinv[node] = dv;
}

// K3: layer-1 scatter, fp16 accumulation. 4 threads/edge; thread q handles
// feats [8q, 8q+8): two coalesced float4 gathers, pack to 4x half2, ONE
// red.v4.f16x2 (16B lane covering 8 feats). 12.8M lanes total (was 25.6M).
__global__ __launch_bounds__(256) void k_scat1() {
    int t = blockIdx.x * 256 + threadIdx.x;      // grid exact: E*4
    int e = t >> 2, q = t & 3;
    int r = g_row[e];
    int c = g_col[e];
    const float* srcp = g_g1 + (size_t)r * HID + q * 8;
    const float4 va = *(const float4*)(srcp);
    const float4 vb = *(const float4*)(srcp + 4);
    __half2 h0 = __floats2half2_rn(va.x, va.y);
    __half2 h1 = __floats2half2_rn(va.z, va.w);
    __half2 h2 = __floats2half2_rn(vb.x, vb.y);
    __half2 h3 = __floats2half2_rn(vb.z, vb.w);
    __half* dst = g_acc1 + (size_t)c * HID + q * 8;
    asm volatile("red.global.add.noftz.v4.f16x2 [%0], {%1,%2,%3,%4};"
                 :: "l"(dst),
                    "r"(*(const unsigned*)&h0), "r"(*(const unsigned*)&h1),
                    "r"(*(const unsigned*)&h2), "r"(*(const unsigned*)&h3)
                 : "memory");
}

// K4: h = relu(acc1*dinv + b1); g2 = dinv * (h @ W2). Warp per node.
__global__ __launch_bounds__(256) void k_fuse(const float* __restrict__ W2,
                                              const float* __restrict__ b1) {
    __shared__ float sW[HID * OUT_C];
    __shared__ float sb1[HID];
    __shared__ float sh[8][HID];
    for (int i = threadIdx.x; i < HID * OUT_C; i += 256) sW[i] = W2[i];
    for (int i = threadIdx.x; i < HID; i += 256) sb1[i] = b1[i];
    __syncthreads();

    int warp = threadIdx.x >> 5, lane = threadIdx.x & 31;
    int node = blockIdx.x * 8 + warp;
    if (node >= N_NODES) return;

    float dv = g_dinv[node];
    float a = __half2float(g_acc1[(size_t)node * HID + lane]);
    float h = fmaxf(fmaf(a, dv, sb1[lane]), 0.0f);
    sh[warp][lane] = h;
    __syncwarp();

    if (lane < OUT_C) {
        float acc = 0.0f;
#pragma unroll
        for (int k = 0; k < HID; k++)
            acc = fmaf(sh[warp][k], sW[k * OUT_C + lane], acc);
        g_g2[(size_t)node * OUT_C + lane] = acc * dv;
    }
}

// K5: layer-2 scatter, fp32 (output-adjacent; precision containment).
// 4 threads/edge, float4 + red.v4.f32.
__global__ __launch_bounds__(256) void k_scat2() {
    int t = blockIdx.x * 256 + threadIdx.x;      // grid exact: E*4
    int e = t >> 2, q = t & 3;
    int r = g_row[e];
    int c = g_col[e];
    const float4 v = *(const float4*)(g_g2 + (size_t)r * OUT_C + q * 4);
    float* dst = g_acc2 + (size_t)c * OUT_C + q * 4;
    asm volatile("red.global.add.v4.f32 [%0], {%1,%2,%3,%4};"
                 :: "l"(dst), "f"(v.x), "f"(v.y), "f"(v.z), "f"(v.w) : "memory");
}

// K6: out = acc2*dinv + b2; zero-fill tail (tuple scalar slot).
__global__ void k_final(float* __restrict__ out, const float* __restrict__ b2,
                        int out_size) {
    int t = blockIdx.x * blockDim.x + threadIdx.x;
    if (t >= out_size) return;
    if (t < N_NODES * OUT_C) {
        int c = t >> 4, j = t & 15;              // OUT_C == 16
        out[t] = g_acc2[t] * g_dinv[c] + b2[j];
    } else {
        out[t] = 0.0f;
    }
}

// ---------------------------------------------------------------------------
extern "C" void kernel_launch(void* const* d_in, const int* in_sizes, int n_in,
                              void* d_out, int out_size) {
    const float* x  = (const float*)d_in[0];
    const void*  ei = d_in[1];
    const float* W1 = (const float*)d_in[2];
    const float* b1 = (const float*)d_in[3];
    const float* W2 = (const float*)d_in[4];
    const float* b2 = (const float*)d_in[5];
    float* out = (float*)d_out;

    void *p_degi, *p_acc1, *p_acc2;
    cudaGetSymbolAddress(&p_degi, g_degi);
    cudaGetSymbolAddress(&p_acc1, g_acc1);
    cudaGetSymbolAddress(&p_acc2, g_acc2);
    cudaMemsetAsync(p_degi, 0, (size_t)N_NODES * sizeof(int));
    cudaMemsetAsync(p_acc1, 0, (size_t)N_NODES * HID * sizeof(__half));
    cudaMemsetAsync(p_acc2, 0, (size_t)N_NODES * OUT_C * sizeof(float));

    k_detect<<<1, 256>>>(ei);
    k_fusedA<<<GEMM_BLOCKS + EDGE_BLOCKS, 256>>>(x, W1, ei);
    k_scale <<<(N_NODES * HID + 255) / 256, 256>>>();
    k_scat1 <<<(N_EDGES * 4) / 256, 256>>>();
    k_fuse  <<<(N_NODES + 7) / 8, 256>>>(W2, b1);
    k_scat2 <<<(N_EDGES * 4) / 256, 256>>>();
    k_final <<<(out_size + 255) / 256, 256>>>(out, b2, out_size);
}

// round 12
// speedup vs baseline: 2.2470x; 1.0403x over previous
#include <cuda_runtime.h>
#include <cuda_fp16.h>
#include <cstdint>

// ---------------------------------------------------------------------------
// GCNEncoder: 2-layer GCN, N=100000, E=3200000, 128 -> 32 -> 16.
//
// R11 = R10 (204.8us) + fp16 layer-2 accumulator + vectorized scale.
// Validated cost model: scatter cost = RED *lane* count (one L1tex wavefront
// per 16B lane, payload-width independent).
//   scat1: fp16 acc row = 64B -> 4 lanes/edge (floor; RED max width 16B).
//   scat2: fp16 acc row = 32B -> 2 lanes/edge (was 4 fp32) -> ~25us.
// Measured precision: layer-1 fp16 acc alone = 3.37e-4; layer-2 adds
// independently -> ~5e-4 total, 2x margin under 1e-3.
// Sorted/CSR designs failed 4x (R3/R5/R7/R8). Do not revisit.
// ---------------------------------------------------------------------------

#define N_NODES 100000
#define N_EDGES 3200000
#define IN_C    128
#define HID     32
#define OUT_C   16

#define GEMM_BLOCKS (N_NODES / 32)    // 3125
#define EDGE_BLOCKS (N_EDGES / 256)   // 12500 (exact)

// Scratch (no cudaMalloc allowed) ------------------------------------------
__device__ int    g_degi[N_NODES];
__device__ int    g_row [N_EDGES];
__device__ int    g_col [N_EDGES];
__device__ float  g_dinv[N_NODES];
__device__ __align__(16) float  g_g1  [N_NODES * HID];   // dinv*(x@W1)
__device__ __align__(16) __half g_acc1[N_NODES * HID];   // fp16 accumulator
__device__ __align__(16) float  g_g2  [N_NODES * OUT_C]; // dinv*(relu@W2)
__device__ __align__(16) __half g_acc2[N_NODES * OUT_C]; // fp16 accumulator
__device__ int    g_is64;

__device__ __forceinline__ int edge_row(const void* ei, int e, int is64) {
    return is64 ? (int)((const long long*)ei)[e] : ((const int*)ei)[e];
}
__device__ __forceinline__ int edge_col(const void* ei, int e, int is64) {
    return is64 ? (int)((const long long*)ei)[(size_t)N_EDGES + e]
                : ((const int*)ei)[(size_t)N_EDGES + e];
}

// K0: dtype detection (int64 view of genuine int32 data leaves [0,N) with
// overwhelming probability across 2048 samples).
__global__ void k_detect(const void* __restrict__ ei) {
    __shared__ int bad;
    if (threadIdx.x == 0) bad = 0;
    __syncthreads();
    const long long* p = (const long long*)ei;
    for (int i = threadIdx.x; i < 2048; i += blockDim.x) {
        long long v = p[i];
        if (v < 0 || v >= N_NODES) atomicOr(&bad, 1);
    }
    __syncthreads();
    if (threadIdx.x == 0) g_is64 = (bad == 0) ? 1 : 0;
}

// K1 (fused): blocks [0,GEMM_BLOCKS) register-tiled g1 = x@W1 (unscaled);
// blocks [GEMM_BLOCKS,+EDGE_BLOCKS) decode indices + degree histogram.
__global__ __launch_bounds__(256) void k_fusedA(const float* __restrict__ x,
                                                const float* __restrict__ W1,
                                                const void*  __restrict__ ei) {
    int tid = threadIdx.x;
    if (blockIdx.x >= GEMM_BLOCKS) {
        int e = (blockIdx.x - GEMM_BLOCKS) * 256 + tid;
        int is64 = g_is64;
        int r = edge_row(ei, e, is64);
        int c = edge_col(ei, e, is64);
        g_row[e] = r;
        g_col[e] = c;
        atomicAdd(&g_degi[c], 1);
        return;
    }
    __shared__ float sW[IN_C * HID];
    __shared__ float sx[32][IN_C];
#pragma unroll
    for (int i = tid; i < (IN_C * HID) / 4; i += 256)
        ((float4*)sW)[i] = ((const float4*)W1)[i];

    int nb = blockIdx.x * 32;
#pragma unroll
    for (int i = tid; i < 32 * (IN_C / 4); i += 256) {
        int row = i >> 5, c4 = i & 31;
        ((float4*)sx[row])[c4] =
            ((const float4*)(x + (size_t)(nb + row) * IN_C))[c4];
    }
    __syncthreads();

    int warp = tid >> 5, lane = tid & 31;
    int n0 = warp * 4;
    float a0 = 0.f, a1 = 0.f, a2 = 0.f, a3 = 0.f;
#pragma unroll 4
    for (int kk = 0; kk < IN_C; kk += 4) {
        float4 xa = *(const float4*)&sx[n0 + 0][kk];
        float4 xb = *(const float4*)&sx[n0 + 1][kk];
        float4 xc = *(const float4*)&sx[n0 + 2][kk];
        float4 xd = *(const float4*)&sx[n0 + 3][kk];
        float w0 = sW[(kk + 0) * HID + lane];
        float w1 = sW[(kk + 1) * HID + lane];
        float w2 = sW[(kk + 2) * HID + lane];
        float w3 = sW[(kk + 3) * HID + lane];
        a0 = fmaf(xa.x, w0, fmaf(xa.y, w1, fmaf(xa.z, w2, fmaf(xa.w, w3, a0))));
        a1 = fmaf(xb.x, w0, fmaf(xb.y, w1, fmaf(xb.z, w2, fmaf(xb.w, w3, a1))));
        a2 = fmaf(xc.x, w0, fmaf(xc.y, w1, fmaf(xc.z, w2, fmaf(xc.w, w3, a2))));
        a3 = fmaf(xd.x, w0, fmaf(xd.y, w1, fmaf(xd.z, w2, fmaf(xd.w, w3, a3))));
    }
    g_g1[(size_t)(nb + n0 + 0) * HID + lane] = a0;
    g_g1[(size_t)(nb + n0 + 1) * HID + lane] = a1;
    g_g1[(size_t)(nb + n0 + 2) * HID + lane] = a2;
    g_g1[(size_t)(nb + n0 + 3) * HID + lane] = a3;
}

// K2: dinv = rsqrt(deg) (or 0); scale g1 in place, float4 per thread.
__global__ void k_scale() {
    int i = blockIdx.x * blockDim.x + threadIdx.x;   // float4 index
    if (i >= N_NODES * HID / 4) return;
    int node = i >> 3;                               // 8 float4 per 32-f row
    int d = g_degi[node];
    float dv = (d > 0) ? rsqrtf((float)d) : 0.0f;
    float4 v = ((const float4*)g_g1)[i];
    v.x *= dv; v.y *= dv; v.z *= dv; v.w *= dv;
    ((float4*)g_g1)[i] = v;
    if ((i & 7) == 0) g_dinv[node] = dv;
}

// K3: layer-1 scatter, fp16 accumulation. 4 threads/edge; thread q covers
// feats [8q,8q+8): two coalesced float4 gathers -> 4x half2 -> ONE
// red.v4.f16x2 (16B lane). 12.8M lanes (floor for 64B fp16 rows).
__global__ __launch_bounds__(256) void k_scat1() {
    int t = blockIdx.x * 256 + threadIdx.x;      // grid exact: E*4
    int e = t >> 2, q = t & 3;
    int r = g_row[e];
    int c = g_col[e];
    const float* srcp = g_g1 + (size_t)r * HID + q * 8;
    const float4 va = *(const float4*)(srcp);
    const float4 vb = *(const float4*)(srcp + 4);
    __half2 h0 = __floats2half2_rn(va.x, va.y);
    __half2 h1 = __floats2half2_rn(va.z, va.w);
    __half2 h2 = __floats2half2_rn(vb.x, vb.y);
    __half2 h3 = __floats2half2_rn(vb.z, vb.w);
    __half* dst = g_acc1 + (size_t)c * HID + q * 8;
    asm volatile("red.global.add.noftz.v4.f16x2 [%0], {%1,%2,%3,%4};"
                 :: "l"(dst),
                    "r"(*(const unsigned*)&h0), "r"(*(const unsigned*)&h1),
                    "r"(*(const unsigned*)&h2), "r"(*(const unsigned*)&h3)
                 : "memory");
}

// K4: h = relu(acc1*dinv + b1); g2 = dinv * (h @ W2). Warp per node.
__global__ __launch_bounds__(256) void k_fuse(const float* __restrict__ W2,
                                              const float* __restrict__ b1) {
    __shared__ float sW[HID * OUT_C];
    __shared__ float sb1[HID];
    __shared__ float sh[8][HID];
    for (int i = threadIdx.x; i < HID * OUT_C; i += 256) sW[i] = W2[i];
    for (int i = threadIdx.x; i < HID; i += 256) sb1[i] = b1[i];
    __syncthreads();

    int warp = threadIdx.x >> 5, lane = threadIdx.x & 31;
    int node = blockIdx.x * 8 + warp;
    if (node >= N_NODES) return;

    float dv = g_dinv[node];
    float a = __half2float(g_acc1[(size_t)node * HID + lane]);
    float h = fmaxf(fmaf(a, dv, sb1[lane]), 0.0f);
    sh[warp][lane] = h;
    __syncwarp();

    if (lane < OUT_C) {
        float acc = 0.0f;
#pragma unroll
        for (int k = 0; k < HID; k++)
            acc = fmaf(sh[warp][k], sW[k * OUT_C + lane], acc);
        g_g2[(size_t)node * OUT_C + lane] = acc * dv;
    }
}

// K5: layer-2 scatter, fp16 accumulation. 2 threads/edge; thread q covers
// feats [8q,8q+8): two float4 gathers -> ONE red.v4.f16x2. 6.4M lanes.
__global__ __launch_bounds__(256) void k_scat2() {
    int t = blockIdx.x * 256 + threadIdx.x;      // grid exact: E*2
    int e = t >> 1, q = t & 1;
    int r = g_row[e];
    int c = g_col[e];
    const float* srcp = g_g2 + (size_t)r * OUT_C + q * 8;
    const float4 va = *(const float4*)(srcp);
    const float4 vb = *(const float4*)(srcp + 4);
    __half2 h0 = __floats2half2_rn(va.x, va.y);
    __half2 h1 = __floats2half2_rn(va.z, va.w);
    __half2 h2 = __floats2half2_rn(vb.x, vb.y);
    __half2 h3 = __floats2half2_rn(vb.z, vb.w);
    __half* dst = g_acc2 + (size_t)c * OUT_C + q * 8;
    asm volatile("red.global.add.noftz.v4.f16x2 [%0], {%1,%2,%3,%4};"
                 :: "l"(dst),
                    "r"(*(const unsigned*)&h0), "r"(*(const unsigned*)&h1),
                    "r"(*(const unsigned*)&h2), "r"(*(const unsigned*)&h3)
                 : "memory");
}

// K6: out = acc2*dinv + b2; zero-fill tail (tuple scalar slot).
__global__ void k_final(float* __restrict__ out, const float* __restrict__ b2,
                        int out_size) {
    int t = blockIdx.x * blockDim.x + threadIdx.x;
    if (t >= out_size) return;
    if (t < N_NODES * OUT_C) {
        int c = t >> 4, j = t & 15;              // OUT_C == 16
        out[t] = __half2float(g_acc2[t]) * g_dinv[c] + b2[j];
    } else {
        out[t] = 0.0f;
    }
}

// ---------------------------------------------------------------------------
extern "C" void kernel_launch(void* const* d_in, const int* in_sizes, int n_in,
                              void* d_out, int out_size) {
    const float* x  = (const float*)d_in[0];
    const void*  ei = d_in[1];
    const float* W1 = (const float*)d_in[2];
    const float* b1 = (const float*)d_in[3];
    const float* W2 = (const float*)d_in[4];
    const float* b2 = (const float*)d_in[5];
    float* out = (float*)d_out;

    void *p_degi, *p_acc1, *p_acc2;
    cudaGetSymbolAddress(&p_degi, g_degi);
    cudaGetSymbolAddress(&p_acc1, g_acc1);
    cudaGetSymbolAddress(&p_acc2, g_acc2);
    cudaMemsetAsync(p_degi, 0, (size_t)N_NODES * sizeof(int));
    cudaMemsetAsync(p_acc1, 0, (size_t)N_NODES * HID * sizeof(__half));
    cudaMemsetAsync(p_acc2, 0, (size_t)N_NODES * OUT_C * sizeof(__half));

    k_detect<<<1, 256>>>(ei);
    k_fusedA<<<GEMM_BLOCKS + EDGE_BLOCKS, 256>>>(x, W1, ei);
    k_scale <<<(N_NODES * HID / 4 + 255) / 256, 256>>>();
    k_scat1 <<<(N_EDGES * 4) / 256, 256>>>();
    k_fuse  <<<(N_NODES + 7) / 8, 256>>>(W2, b1);
    k_scat2 <<<(N_EDGES * 2) / 256, 256>>>();
    k_final <<<(out_size + 255) / 256, 256>>>(out, b2, out_size);
}

// round 13
// speedup vs baseline: 2.3171x; 1.0312x over previous
#include <cuda_runtime.h>
#include <cuda_fp16.h>
#include <cstdint>

// ---------------------------------------------------------------------------
// GCNEncoder: 2-layer GCN, N=100000, E=3200000, 128 -> 32 -> 16.
//
// R12 = R11 (196.9us) + banked fp16 accumulators + fp16 feature tables.
//  * Banking: B parity-selected banks cut fp16 accumulation error ~1/B at
//    ZERO extra RED lanes. acc1: 2 banks (1.7e-4), acc2: 4 banks (1.8e-4).
//    R11's 8.03e-4 margin was too thin under nondeterministic RED order.
//  * g1/g2 stored fp16: scat gathers become one uint4 + direct f16x2 RED
//    (no CVT chain -- R11 scat1 alu=11.8% was the pack overhead).
// Validated cost model: scatter cost = RED lane count (16B L1tex wavefront
// per lane, payload independent). scat1 floor = 4 lanes/edge, scat2 = 2.
// Sorted/CSR designs failed 4x (R3/R5/R7/R8). Do not revisit.
// ---------------------------------------------------------------------------

#define N_NODES 100000
#define N_EDGES 3200000
#define IN_C    128
#define HID     32
#define OUT_C   16

#define GEMM_BLOCKS (N_NODES / 32)    // 3125
#define EDGE_BLOCKS (N_EDGES / 256)   // 12500 (exact)

#define ACC1_BANK ((size_t)N_NODES * HID)     // elements per bank
#define ACC2_BANK ((size_t)N_NODES * OUT_C)

// Scratch (no cudaMalloc allowed) ------------------------------------------
__device__ int    g_degi[N_NODES];
__device__ int    g_row [N_EDGES];
__device__ int    g_col [N_EDGES];
__device__ float  g_dinv[N_NODES];
__device__ __align__(16) float  g_g1 [N_NODES * HID];      // fp32 x@W1 (pre-scale)
__device__ __align__(16) __half g_g1h[N_NODES * HID];      // fp16 dinv*(x@W1)
__device__ __align__(16) __half g_acc1[2 * N_NODES * HID]; // 2 banks
__device__ __align__(16) __half g_g2h[N_NODES * OUT_C];    // fp16 dinv*(relu@W2)
__device__ __align__(16) __half g_acc2[4 * N_NODES * OUT_C]; // 4 banks
__device__ int    g_is64;

__device__ __forceinline__ int edge_row(const void* ei, int e, int is64) {
    return is64 ? (int)((const long long*)ei)[e] : ((const int*)ei)[e];
}
__device__ __forceinline__ int edge_col(const void* ei, int e, int is64) {
    return is64 ? (int)((const long long*)ei)[(size_t)N_EDGES + e]
                : ((const int*)ei)[(size_t)N_EDGES + e];
}

__device__ __forceinline__ void red_f16x8(__half* dst, uint4 v) {
    asm volatile("red.global.add.noftz.v4.f16x2 [%0], {%1,%2,%3,%4};"
                 :: "l"(dst), "r"(v.x), "r"(v.y), "r"(v.z), "r"(v.w) : "memory");
}

// K0: dtype detection (int64 view of genuine int32 data leaves [0,N) with
// overwhelming probability across 2048 samples).
__global__ void k_detect(const void* __restrict__ ei) {
    __shared__ int bad;
    if (threadIdx.x == 0) bad = 0;
    __syncthreads();
    const long long* p = (const long long*)ei;
    for (int i = threadIdx.x; i < 2048; i += blockDim.x) {
        long long v = p[i];
        if (v < 0 || v >= N_NODES) atomicOr(&bad, 1);
    }
    __syncthreads();
    if (threadIdx.x == 0) g_is64 = (bad == 0) ? 1 : 0;
}

// K1 (fused): blocks [0,GEMM_BLOCKS) register-tiled g1 = x@W1 (fp32, unscaled);
// blocks [GEMM_BLOCKS,+EDGE_BLOCKS) decode indices + degree histogram.
__global__ __launch_bounds__(256) void k_fusedA(const float* __restrict__ x,
                                                const float* __restrict__ W1,
                                                const void*  __restrict__ ei) {
    int tid = threadIdx.x;
    if (blockIdx.x >= GEMM_BLOCKS) {
        int e = (blockIdx.x - GEMM_BLOCKS) * 256 + tid;
        int is64 = g_is64;
        int r = edge_row(ei, e, is64);
        int c = edge_col(ei, e, is64);
        g_row[e] = r;
        g_col[e] = c;
        atomicAdd(&g_degi[c], 1);
        return;
    }
    __shared__ float sW[IN_C * HID];
    __shared__ float sx[32][IN_C];
#pragma unroll
    for (int i = tid; i < (IN_C * HID) / 4; i += 256)
        ((float4*)sW)[i] = ((const float4*)W1)[i];

    int nb = blockIdx.x * 32;
#pragma unroll
    for (int i = tid; i < 32 * (IN_C / 4); i += 256) {
        int row = i >> 5, c4 = i & 31;
        ((float4*)sx[row])[c4] =
            ((const float4*)(x + (size_t)(nb + row) * IN_C))[c4];
    }
    __syncthreads();

    int warp = tid >> 5, lane = tid & 31;
    int n0 = warp * 4;
    float a0 = 0.f, a1 = 0.f, a2 = 0.f, a3 = 0.f;
#pragma unroll 4
    for (int kk = 0; kk < IN_C; kk += 4) {
        float4 xa = *(const float4*)&sx[n0 + 0][kk];
        float4 xb = *(const float4*)&sx[n0 + 1][kk];
        float4 xc = *(const float4*)&sx[n0 + 2][kk];
        float4 xd = *(const float4*)&sx[n0 + 3][kk];
        float w0 = sW[(kk + 0) * HID + lane];
        float w1 = sW[(kk + 1) * HID + lane];
        float w2 = sW[(kk + 2) * HID + lane];
        float w3 = sW[(kk + 3) * HID + lane];
        a0 = fmaf(xa.x, w0, fmaf(xa.y, w1, fmaf(xa.z, w2, fmaf(xa.w, w3, a0))));
        a1 = fmaf(xb.x, w0, fmaf(xb.y, w1, fmaf(xb.z, w2, fmaf(xb.w, w3, a1))));
        a2 = fmaf(xc.x, w0, fmaf(xc.y, w1, fmaf(xc.z, w2, fmaf(xc.w, w3, a2))));
        a3 = fmaf(xd.x, w0, fmaf(xd.y, w1, fmaf(xd.z, w2, fmaf(xd.w, w3, a3))));
    }
    g_g1[(size_t)(nb + n0 + 0) * HID + lane] = a0;
    g_g1[(size_t)(nb + n0 + 1) * HID + lane] = a1;
    g_g1[(size_t)(nb + n0 + 2) * HID + lane] = a2;
    g_g1[(size_t)(nb + n0 + 3) * HID + lane] = a3;
}

// K2: dinv = rsqrt(deg) (or 0); g1h = fp16(dinv * g1). 8 floats per thread.
__global__ void k_scale() {
    int i = blockIdx.x * blockDim.x + threadIdx.x;   // 8-float chunk index
    if (i >= N_NODES * HID / 8) return;
    int node = i >> 2;                               // 4 chunks per 32-f row
    int d = g_degi[node];
    float dv = (d > 0) ? rsqrtf((float)d) : 0.0f;
    const float4 a = ((const float4*)g_g1)[i * 2];
    const float4 b = ((const float4*)g_g1)[i * 2 + 1];
    uint4 o;
    *(__half2*)&o.x = __floats2half2_rn(a.x * dv, a.y * dv);
    *(__half2*)&o.y = __floats2half2_rn(a.z * dv, a.w * dv);
    *(__half2*)&o.z = __floats2half2_rn(b.x * dv, b.y * dv);
    *(__half2*)&o.w = __floats2half2_rn(b.z * dv, b.w * dv);
    ((uint4*)g_g1h)[i] = o;
    if ((i & 3) == 0) g_dinv[node] = dv;
}

// K3: layer-1 scatter. 4 threads/edge; thread q: ONE uint4 fp16 gather
// (8 feats) -> ONE red.v4.f16x2 into parity bank e&1. No CVTs.
__global__ __launch_bounds__(256) void k_scat1() {
    int t = blockIdx.x * 256 + threadIdx.x;      // grid exact: E*4
    int e = t >> 2, q = t & 3;
    int r = g_row[e];
    int c = g_col[e];
    uint4 v = *(const uint4*)(g_g1h + (size_t)r * HID + q * 8);
    __half* dst = g_acc1 + (size_t)(e & 1) * ACC1_BANK + (size_t)c * HID + q * 8;
    red_f16x8(dst, v);
}

// K4: h = relu((bank0+bank1)*dinv + b1); g2h = fp16(dinv*(h@W2)). Warp/node.
__global__ __launch_bounds__(256) void k_fuse(const float* __restrict__ W2,
                                              const float* __restrict__ b1) {
    __shared__ float sW[HID * OUT_C];
    __shared__ float sb1[HID];
    __shared__ float sh[8][HID];
    for (int i = threadIdx.x; i < HID * OUT_C; i += 256) sW[i] = W2[i];
    for (int i = threadIdx.x; i < HID; i += 256) sb1[i] = b1[i];
    __syncthreads();

    int warp = threadIdx.x >> 5, lane = threadIdx.x & 31;
    int node = blockIdx.x * 8 + warp;
    if (node >= N_NODES) return;

    float dv = g_dinv[node];
    size_t idx = (size_t)node * HID + lane;
    float a = __half2float(g_acc1[idx]) + __half2float(g_acc1[ACC1_BANK + idx]);
    float h = fmaxf(fmaf(a, dv, sb1[lane]), 0.0f);
    sh[warp][lane] = h;
    __syncwarp();

    if (lane < OUT_C) {
        float acc = 0.0f;
#pragma unroll
        for (int k = 0; k < HID; k++)
            acc = fmaf(sh[warp][k], sW[k * OUT_C + lane], acc);
        g_g2h[(size_t)node * OUT_C + lane] = __float2half(acc * dv);
    }
}

// K5: layer-2 scatter. 2 threads/edge; thread q: ONE uint4 fp16 gather
// (8 feats) -> ONE red.v4.f16x2 into parity bank e&3.
__global__ __launch_bounds__(256) void k_scat2() {
    int t = blockIdx.x * 256 + threadIdx.x;      // grid exact: E*2
    int e = t >> 1, q = t & 1;
    int r = g_row[e];
    int c = g_col[e];
    uint4 v = *(const uint4*)(g_g2h + (size_t)r * OUT_C + q * 8);
    __half* dst = g_acc2 + (size_t)(e & 3) * ACC2_BANK + (size_t)c * OUT_C + q * 8;
    red_f16x8(dst, v);
}

// K6: out = (sum of 4 banks)*dinv + b2; zero-fill tail (tuple scalar slot).
__global__ void k_final(float* __restrict__ out, const float* __restrict__ b2,
                        int out_size) {
    int t = blockIdx.x * blockDim.x + threadIdx.x;
    if (t >= out_size) return;
    if (t < N_NODES * OUT_C) {
        int c = t >> 4, j = t & 15;              // OUT_C == 16
        float a = (__half2float(g_acc2[t]) +
                   __half2float(g_acc2[ACC2_BANK + t])) +
                  (__half2float(g_acc2[2 * ACC2_BANK + t]) +
                   __half2float(g_acc2[3 * ACC2_BANK + t]));
        out[t] = a * g_dinv[c] + b2[j];
    } else {
        out[t] = 0.0f;
    }
}

// ---------------------------------------------------------------------------
extern "C" void kernel_launch(void* const* d_in, const int* in_sizes, int n_in,
                              void* d_out, int out_size) {
    const float* x  = (const float*)d_in[0];
    const void*  ei = d_in[1];
    const float* W1 = (const float*)d_in[2];
    const float* b1 = (const float*)d_in[3];
    const float* W2 = (const float*)d_in[4];
    const float* b2 = (const float*)d_in[5];
    float* out = (float*)d_out;

    void *p_degi, *p_acc1, *p_acc2;
    cudaGetSymbolAddress(&p_degi, g_degi);
    cudaGetSymbolAddress(&p_acc1, g_acc1);
    cudaGetSymbolAddress(&p_acc2, g_acc2);
    cudaMemsetAsync(p_degi, 0, (size_t)N_NODES * sizeof(int));
    cudaMemsetAsync(p_acc1, 0, 2 * ACC1_BANK * sizeof(__half));
    cudaMemsetAsync(p_acc2, 0, 4 * ACC2_BANK * sizeof(__half));

    k_detect<<<1, 256>>>(ei);
    k_fusedA<<<GEMM_BLOCKS + EDGE_BLOCKS, 256>>>(x, W1, ei);
    k_scale <<<(N_NODES * HID / 8 + 255) / 256, 256>>>();
    k_scat1 <<<(N_EDGES * 4) / 256, 256>>>();
    k_fuse  <<<(N_NODES + 7) / 8, 256>>>(W2, b1);
    k_scat2 <<<(N_EDGES * 2) / 256, 256>>>();
    k_final <<<(out_size + 255) / 256, 256>>>(out, b2, out_size);
}

// round 14
// speedup vs baseline: 2.3941x; 1.0332x over previous
#include <cuda_runtime.h>
#include <cuda_fp16.h>
#include <cstdint>

// ---------------------------------------------------------------------------
// GCNEncoder: 2-layer GCN, N=100000, E=3200000, 128 -> 32 -> 16.
//
// R13 = R12 (190.9us, rel_err 3.7e-4) + real GEMM/edge overlap in k_fusedA.
// R12 profile accounting showed fusedA ~75us: role split by blockIdx range
// made the GEMM waves run BEFORE the edge waves (no co-residency). Now roles
// interleave (bid%3==0 -> GEMM, else edge with 2 edges/thread, vectorized
// int2/longlong2 loads), so FMA-bound GEMM blocks and latency-bound edge
// blocks share every SM from wave 1.
// Validated models:
//  * scatter cost = RED lane count (16B wavefront/lane, payload-indep);
//    scat1 = 4 lanes/edge (floor), scat2 = 2 (floor).
//  * banked fp16 accumulators: error ~ 1/B, zero extra lanes.
// Sorted/CSR designs failed 4x. Do not revisit.
// ---------------------------------------------------------------------------

#define N_NODES 100000
#define N_EDGES 3200000
#define IN_C    128
#define HID     32
#define OUT_C   16

#define GEMM_BLOCKS (N_NODES / 32)     // 3125
#define EDGE_BLOCKS (N_EDGES / 512)    // 6250 (2 edges/thread, exact)
#define FA_BLOCKS   (GEMM_BLOCKS + EDGE_BLOCKS)  // 9375

#define ACC1_BANK ((size_t)N_NODES * HID)
#define ACC2_BANK ((size_t)N_NODES * OUT_C)

// Scratch (no cudaMalloc allowed) ------------------------------------------
__device__ int    g_degi[N_NODES];
__device__ __align__(16) int g_row[N_EDGES];
__device__ __align__(16) int g_col[N_EDGES];
__device__ float  g_dinv[N_NODES];
__device__ __align__(16) float  g_g1 [N_NODES * HID];       // fp32 x@W1
__device__ __align__(16) __half g_g1h[N_NODES * HID];       // fp16 dinv*(x@W1)
__device__ __align__(16) __half g_acc1[2 * N_NODES * HID];  // 2 banks
__device__ __align__(16) __half g_g2h[N_NODES * OUT_C];     // fp16 dinv*(relu@W2)
__device__ __align__(16) __half g_acc2[4 * N_NODES * OUT_C];// 4 banks
__device__ int    g_is64;

__device__ __forceinline__ void red_f16x8(__half* dst, uint4 v) {
    asm volatile("red.global.add.noftz.v4.f16x2 [%0], {%1,%2,%3,%4};"
                 :: "l"(dst), "r"(v.x), "r"(v.y), "r"(v.z), "r"(v.w) : "memory");
}

// K0: dtype detection (int64 view of genuine int32 data leaves [0,N) with
// overwhelming probability across 2048 samples).
__global__ void k_detect(const void* __restrict__ ei) {
    __shared__ int bad;
    if (threadIdx.x == 0) bad = 0;
    __syncthreads();
    const long long* p = (const long long*)ei;
    for (int i = threadIdx.x; i < 2048; i += blockDim.x) {
        long long v = p[i];
        if (v < 0 || v >= N_NODES) atomicOr(&bad, 1);
    }
    __syncthreads();
    if (threadIdx.x == 0) g_is64 = (bad == 0) ? 1 : 0;
}

// K1 (fused, interleaved): bid%3==0 -> GEMM block (id = bid/3) computing
// g1 = x@W1 for 32 nodes; else edge block (id = (bid/3)*2 + bid%3 - 1)
// decoding 512 edges (2/thread) + degree histogram. Roles co-resident.
__global__ __launch_bounds__(256) void k_fusedA(const float* __restrict__ x,
                                                const float* __restrict__ W1,
                                                const void*  __restrict__ ei) {
    int tid = threadIdx.x;
    int g = blockIdx.x % 3;
    if (g != 0) {
        // ---- edge half: 2 edges per thread, vectorized ----
        int eb = (blockIdx.x / 3) * 2 + (g - 1);      // 0..6249
        int t  = eb * 256 + tid;                      // pair index, 0..1.6M-1
        int r0, r1, c0, c1;
        if (g_is64) {
            longlong2 rr = ((const longlong2*)ei)[t];
            longlong2 cc = ((const longlong2*)ei)[N_EDGES / 2 + t];
            r0 = (int)rr.x; r1 = (int)rr.y;
            c0 = (int)cc.x; c1 = (int)cc.y;
        } else {
            int2 rr = ((const int2*)ei)[t];
            int2 cc = ((const int2*)ei)[N_EDGES / 2 + t];
            r0 = rr.x; r1 = rr.y; c0 = cc.x; c1 = cc.y;
        }
        ((int2*)g_row)[t] = make_int2(r0, r1);
        ((int2*)g_col)[t] = make_int2(c0, c1);
        atomicAdd(&g_degi[c0], 1);
        atomicAdd(&g_degi[c1], 1);
        return;
    }
    // ---- GEMM half: register-tiled, warp = 4 nodes x 32 features ----
    __shared__ float sW[IN_C * HID];
    __shared__ float sx[32][IN_C];
#pragma unroll
    for (int i = tid; i < (IN_C * HID) / 4; i += 256)
        ((float4*)sW)[i] = ((const float4*)W1)[i];

    int nb = (blockIdx.x / 3) * 32;
#pragma unroll
    for (int i = tid; i < 32 * (IN_C / 4); i += 256) {
        int row = i >> 5, c4 = i & 31;
        ((float4*)sx[row])[c4] =
            ((const float4*)(x + (size_t)(nb + row) * IN_C))[c4];
    }
    __syncthreads();

    int warp = tid >> 5, lane = tid & 31;
    int n0 = warp * 4;
    float a0 = 0.f, a1 = 0.f, a2 = 0.f, a3 = 0.f;
#pragma unroll 4
    for (int kk = 0; kk < IN_C; kk += 4) {
        float4 xa = *(const float4*)&sx[n0 + 0][kk];
        float4 xb = *(const float4*)&sx[n0 + 1][kk];
        float4 xc = *(const float4*)&sx[n0 + 2][kk];
        float4 xd = *(const float4*)&sx[n0 + 3][kk];
        float w0 = sW[(kk + 0) * HID + lane];
        float w1 = sW[(kk + 1) * HID + lane];
        float w2 = sW[(kk + 2) * HID + lane];
        float w3 = sW[(kk + 3) * HID + lane];
        a0 = fmaf(xa.x, w0, fmaf(xa.y, w1, fmaf(xa.z, w2, fmaf(xa.w, w3, a0))));
        a1 = fmaf(xb.x, w0, fmaf(xb.y, w1, fmaf(xb.z, w2, fmaf(xb.w, w3, a1))));
        a2 = fmaf(xc.x, w0, fmaf(xc.y, w1, fmaf(xc.z, w2, fmaf(xc.w, w3, a2))));
        a3 = fmaf(xd.x, w0, fmaf(xd.y, w1, fmaf(xd.z, w2, fmaf(xd.w, w3, a3))));
    }
    g_g1[(size_t)(nb + n0 + 0) * HID + lane] = a0;
    g_g1[(size_t)(nb + n0 + 1) * HID + lane] = a1;
    g_g1[(size_t)(nb + n0 + 2) * HID + lane] = a2;
    g_g1[(size_t)(nb + n0 + 3) * HID + lane] = a3;
}

// K2: dinv = rsqrt(deg) (or 0); g1h = fp16(dinv * g1). 8 floats per thread.
__global__ void k_scale() {
    int i = blockIdx.x * blockDim.x + threadIdx.x;   // 8-float chunk index
    if (i >= N_NODES * HID / 8) return;
    int node = i >> 2;                               // 4 chunks per 32-f row
    int d = g_degi[node];
    float dv = (d > 0) ? rsqrtf((float)d) : 0.0f;
    const float4 a = ((const float4*)g_g1)[i * 2];
    const float4 b = ((const float4*)g_g1)[i * 2 + 1];
    uint4 o;
    *(__half2*)&o.x = __floats2half2_rn(a.x * dv, a.y * dv);
    *(__half2*)&o.y = __floats2half2_rn(a.z * dv, a.w * dv);
    *(__half2*)&o.z = __floats2half2_rn(b.x * dv, b.y * dv);
    *(__half2*)&o.w = __floats2half2_rn(b.z * dv, b.w * dv);
    ((uint4*)g_g1h)[i] = o;
    if ((i & 3) == 0) g_dinv[node] = dv;
}

// K3: layer-1 scatter. 4 threads/edge; thread q: ONE uint4 fp16 gather
// (8 feats) -> ONE red.v4.f16x2 into parity bank e&1.
__global__ __launch_bounds__(256) void k_scat1() {
    int t = blockIdx.x * 256 + threadIdx.x;      // grid exact: E*4
    int e = t >> 2, q = t & 3;
    int r = g_row[e];
    int c = g_col[e];
    uint4 v = *(const uint4*)(g_g1h + (size_t)r * HID + q * 8);
    __half* dst = g_acc1 + (size_t)(e & 1) * ACC1_BANK + (size_t)c * HID + q * 8;
    red_f16x8(dst, v);
}

// K4: h = relu((bank0+bank1)*dinv + b1); g2h = fp16(dinv*(h@W2)). Warp/node.
__global__ __launch_bounds__(256) void k_fuse(const float* __restrict__ W2,
                                              const float* __restrict__ b1) {
    __shared__ float sW[HID * OUT_C];
    __shared__ float sb1[HID];
    __shared__ float sh[8][HID];
    for (int i = threadIdx.x; i < HID * OUT_C; i += 256) sW[i] = W2[i];
    for (int i = threadIdx.x; i < HID; i += 256) sb1[i] = b1[i];
    __syncthreads();

    int warp = threadIdx.x >> 5, lane = threadIdx.x & 31;
    int node = blockIdx.x * 8 + warp;
    if (node >= N_NODES) return;

    float dv = g_dinv[node];
    size_t idx = (size_t)node * HID + lane;
    float a = __half2float(g_acc1[idx]) + __half2float(g_acc1[ACC1_BANK + idx]);
    float h = fmaxf(fmaf(a, dv, sb1[lane]), 0.0f);
    sh[warp][lane] = h;
    __syncwarp();

    if (lane < OUT_C) {
        float acc = 0.0f;
#pragma unroll
        for (int k = 0; k < HID; k++)
            acc = fmaf(sh[warp][k], sW[k * OUT_C + lane], acc);
        g_g2h[(size_t)node * OUT_C + lane] = __float2half(acc * dv);
    }
}

// K5: layer-2 scatter. 2 threads/edge; thread q: ONE uint4 fp16 gather
// (8 feats) -> ONE red.v4.f16x2 into parity bank e&3.
__global__ __launch_bounds__(256) void k_scat2() {
    int t = blockIdx.x * 256 + threadIdx.x;      // grid exact: E*2
    int e = t >> 1, q = t & 1;
    int r = g_row[e];
    int c = g_col[e];
    uint4 v = *(const uint4*)(g_g2h + (size_t)r * OUT_C + q * 8);
    __half* dst = g_acc2 + (size_t)(e & 3) * ACC2_BANK + (size_t)c * OUT_C + q * 8;
    red_f16x8(dst, v);
}

// K6: out = (sum of 4 banks)*dinv + b2; zero-fill tail (tuple scalar slot).
__global__ void k_final(float* __restrict__ out, const float* __restrict__ b2,
                        int out_size) {
    int t = blockIdx.x * blockDim.x + threadIdx.x;
    if (t >= out_size) return;
    if (t < N_NODES * OUT_C) {
        int c = t >> 4, j = t & 15;              // OUT_C == 16
        float a = (__half2float(g_acc2[t]) +
                   __half2float(g_acc2[ACC2_BANK + t])) +
                  (__half2float(g_acc2[2 * ACC2_BANK + t]) +
                   __half2float(g_acc2[3 * ACC2_BANK + t]));
        out[t] = a * g_dinv[c] + b2[j];
    } else {
        out[t] = 0.0f;
    }
}

// ---------------------------------------------------------------------------
extern "C" void kernel_launch(void* const* d_in, const int* in_sizes, int n_in,
                              void* d_out, int out_size) {
    const float* x  = (const float*)d_in[0];
    const void*  ei = d_in[1];
    const float* W1 = (const float*)d_in[2];
    const float* b1 = (const float*)d_in[3];
    const float* W2 = (const float*)d_in[4];
    const float* b2 = (const float*)d_in[5];
    float* out = (float*)d_out;

    void *p_degi, *p_acc1, *p_acc2;
    cudaGetSymbolAddress(&p_degi, g_degi);
    cudaGetSymbolAddress(&p_acc1, g_acc1);
    cudaGetSymbolAddress(&p_acc2, g_acc2);
    cudaMemsetAsync(p_degi, 0, (size_t)N_NODES * sizeof(int));
    cudaMemsetAsync(p_acc1, 0, 2 * ACC1_BANK * sizeof(__half));
    cudaMemsetAsync(p_acc2, 0, 4 * ACC2_BANK * sizeof(__half));

    k_detect<<<1, 256>>>(ei);
    k_fusedA<<<FA_BLOCKS, 256>>>(x, W1, ei);
    k_scale <<<(N_NODES * HID / 8 + 255) / 256, 256>>>();
    k_scat1 <<<(N_EDGES * 4) / 256, 256>>>();
    k_fuse  <<<(N_NODES + 7) / 8, 256>>>(W2, b1);
    k_scat2 <<<(N_EDGES * 2) / 256, 256>>>();
    k_final <<<(out_size + 255) / 256, 256>>>(out, b2, out_size);
}

// round 15
// speedup vs baseline: 2.4545x; 1.0252x over previous
#include <cuda_runtime.h>
#include <cuda_fp16.h>
#include <cstdint>

// ---------------------------------------------------------------------------
// GCNEncoder: 2-layer GCN, N=100000, E=3200000, 128 -> 32 -> 16.
//
// R14 = R13 (184.8us) + fully-uniform fusedA blocks.
// R13's bid%3 interleave only partially overlapped GEMM and edge work
// (wave-type skew). Now EVERY block does both: decode 1024 edges (4/thread,
// int4/longlong2 vectorized, fire-and-forget histogram REDs) THEN its
// 32-node GEMM tile -- edge latency hides under other warps' FMAs on the
// same SM. Dtype detection folded in per-block (256 int64 probes +
// __syncthreads_or; misdetect prob (1e-5)^256 ~ 0) -> k_detect launch gone.
// Validated models:
//  * scatter cost = RED lane count (16B wavefront/lane, payload-indep);
//    scat1 = 4 lanes/edge (floor), scat2 = 2 (floor).
//  * banked fp16 accumulators: error ~ 1/B, zero extra lanes.
// Sorted/CSR designs failed 4x. Do not revisit.
// ---------------------------------------------------------------------------

#define N_NODES 100000
#define N_EDGES 3200000
#define IN_C    128
#define HID     32
#define OUT_C   16

#define FA_BLOCKS (N_NODES / 32)       // 3125; also E/1024 = 3125 exactly

#define ACC1_BANK ((size_t)N_NODES * HID)
#define ACC2_BANK ((size_t)N_NODES * OUT_C)

// Scratch (no cudaMalloc allowed) ------------------------------------------
__device__ int    g_degi[N_NODES];
__device__ __align__(16) int g_row[N_EDGES];
__device__ __align__(16) int g_col[N_EDGES];
__device__ float  g_dinv[N_NODES];
__device__ __align__(16) float  g_g1 [N_NODES * HID];       // fp32 x@W1
__device__ __align__(16) __half g_g1h[N_NODES * HID];       // fp16 dinv*(x@W1)
__device__ __align__(16) __half g_acc1[2 * N_NODES * HID];  // 2 banks
__device__ __align__(16) __half g_g2h[N_NODES * OUT_C];     // fp16 dinv*(relu@W2)
__device__ __align__(16) __half g_acc2[4 * N_NODES * OUT_C];// 4 banks

__device__ __forceinline__ void red_f16x8(__half* dst, uint4 v) {
    asm volatile("red.global.add.noftz.v4.f16x2 [%0], {%1,%2,%3,%4};"
                 :: "l"(dst), "r"(v.x), "r"(v.y), "r"(v.z), "r"(v.w) : "memory");
}

// K1 (uniform fused): every block = [dtype detect] + [1024-edge decode +
// degree histogram] + [32-node register-tiled GEMM tile].
__global__ __launch_bounds__(256) void k_fusedA(const float* __restrict__ x,
                                                const float* __restrict__ W1,
                                                const void*  __restrict__ ei) {
    int tid = threadIdx.x;

    // ---- dtype detection: 256 int64 probes, block-uniform result ----
    // int64 view of genuine int32 data = lo + hi*2^32, out of [0,N) unless
    // hi==0 (p=1e-5); 256 probes -> misdetect prob ~0. All blocks agree.
    long long probe = ((const long long*)ei)[tid];
    int is64 = !__syncthreads_or(probe < 0 || probe >= N_NODES);

    // ---- edge phase: 4 edges/thread, vectorized, fire-and-forget ----
    {
        int t = blockIdx.x * 256 + tid;           // quad index; e0 = 4t
        int4 rr, cc;
        if (is64) {
            longlong2 a = ((const longlong2*)ei)[t * 2];
            longlong2 b = ((const longlong2*)ei)[t * 2 + 1];
            longlong2 c = ((const longlong2*)ei)[N_EDGES / 2 + t * 2];
            longlong2 d = ((const longlong2*)ei)[N_EDGES / 2 + t * 2 + 1];
            rr = make_int4((int)a.x, (int)a.y, (int)b.x, (int)b.y);
            cc = make_int4((int)c.x, (int)c.y, (int)d.x, (int)d.y);
        } else {
            rr = ((const int4*)ei)[t];
            cc = ((const int4*)ei)[N_EDGES / 4 + t];
        }
        ((int4*)g_row)[t] = rr;
        ((int4*)g_col)[t] = cc;
        atomicAdd(&g_degi[cc.x], 1);
        atomicAdd(&g_degi[cc.y], 1);
        atomicAdd(&g_degi[cc.z], 1);
        atomicAdd(&g_degi[cc.w], 1);
    }

    // ---- GEMM phase: warp = 4 nodes x 32 features ----
    __shared__ float sW[IN_C * HID];
    __shared__ float sx[32][IN_C];
#pragma unroll
    for (int i = tid; i < (IN_C * HID) / 4; i += 256)
        ((float4*)sW)[i] = ((const float4*)W1)[i];

    int nb = blockIdx.x * 32;
#pragma unroll
    for (int i = tid; i < 32 * (IN_C / 4); i += 256) {
        int row = i >> 5, c4 = i & 31;
        ((float4*)sx[row])[c4] =
            ((const float4*)(x + (size_t)(nb + row) * IN_C))[c4];
    }
    __syncthreads();

    int warp = tid >> 5, lane = tid & 31;
    int n0 = warp * 4;
    float a0 = 0.f, a1 = 0.f, a2 = 0.f, a3 = 0.f;
#pragma unroll 4
    for (int kk = 0; kk < IN_C; kk += 4) {
        float4 xa = *(const float4*)&sx[n0 + 0][kk];
        float4 xb = *(const float4*)&sx[n0 + 1][kk];
        float4 xc = *(const float4*)&sx[n0 + 2][kk];
        float4 xd = *(const float4*)&sx[n0 + 3][kk];
        float w0 = sW[(kk + 0) * HID + lane];
        float w1 = sW[(kk + 1) * HID + lane];
        float w2 = sW[(kk + 2) * HID + lane];
        float w3 = sW[(kk + 3) * HID + lane];
        a0 = fmaf(xa.x, w0, fmaf(xa.y, w1, fmaf(xa.z, w2, fmaf(xa.w, w3, a0))));
        a1 = fmaf(xb.x, w0, fmaf(xb.y, w1, fmaf(xb.z, w2, fmaf(xb.w, w3, a1))));
        a2 = fmaf(xc.x, w0, fmaf(xc.y, w1, fmaf(xc.z, w2, fmaf(xc.w, w3, a2))));
        a3 = fmaf(xd.x, w0, fmaf(xd.y, w1, fmaf(xd.z, w2, fmaf(xd.w, w3, a3))));
    }
    g_g1[(size_t)(nb + n0 + 0) * HID + lane] = a0;
    g_g1[(size_t)(nb + n0 + 1) * HID + lane] = a1;
    g_g1[(size_t)(nb + n0 + 2) * HID + lane] = a2;
    g_g1[(size_t)(nb + n0 + 3) * HID + lane] = a3;
}

// K2: dinv = rsqrt(deg) (or 0); g1h = fp16(dinv * g1). 8 floats per thread.
__global__ void k_scale() {
    int i = blockIdx.x * blockDim.x + threadIdx.x;   // 8-float chunk index
    if (i >= N_NODES * HID / 8) return;
    int node = i >> 2;                               // 4 chunks per 32-f row
    int d = g_degi[node];
    float dv = (d > 0) ? rsqrtf((float)d) : 0.0f;
    const float4 a = ((const float4*)g_g1)[i * 2];
    const float4 b = ((const float4*)g_g1)[i * 2 + 1];
    uint4 o;
    *(__half2*)&o.x = __floats2half2_rn(a.x * dv, a.y * dv);
    *(__half2*)&o.y = __floats2half2_rn(a.z * dv, a.w * dv);
    *(__half2*)&o.z = __floats2half2_rn(b.x * dv, b.y * dv);
    *(__half2*)&o.w = __floats2half2_rn(b.z * dv, b.w * dv);
    ((uint4*)g_g1h)[i] = o;
    if ((i & 3) == 0) g_dinv[node] = dv;
}

// K3: layer-1 scatter. 4 threads/edge; thread q: ONE uint4 fp16 gather
// (8 feats) -> ONE red.v4.f16x2 into parity bank e&1.
__global__ __launch_bounds__(256) void k_scat1() {
    int t = blockIdx.x * 256 + threadIdx.x;      // grid exact: E*4
    int e = t >> 2, q = t & 3;
    int r = g_row[e];
    int c = g_col[e];
    uint4 v = *(const uint4*)(g_g1h + (size_t)r * HID + q * 8);
    __half* dst = g_acc1 + (size_t)(e & 1) * ACC1_BANK + (size_t)c * HID + q * 8;
    red_f16x8(dst, v);
}

// K4: h = relu((bank0+bank1)*dinv + b1); g2h = fp16(dinv*(h@W2)). Warp/node.
__global__ __launch_bounds__(256) void k_fuse(const float* __restrict__ W2,
                                              const float* __restrict__ b1) {
    __shared__ float sW[HID * OUT_C];
    __shared__ float sb1[HID];
    __shared__ float sh[8][HID];
    for (int i = threadIdx.x; i < HID * OUT_C; i += 256) sW[i] = W2[i];
    for (int i = threadIdx.x; i < HID; i += 256) sb1[i] = b1[i];
    __syncthreads();

    int warp = threadIdx.x >> 5, lane = threadIdx.x & 31;
    int node = blockIdx.x * 8 + warp;
    if (node >= N_NODES) return;

    float dv = g_dinv[node];
    size_t idx = (size_t)node * HID + lane;
    float a = __half2float(g_acc1[idx]) + __half2float(g_acc1[ACC1_BANK + idx]);
    float h = fmaxf(fmaf(a, dv, sb1[lane]), 0.0f);
    sh[warp][lane] = h;
    __syncwarp();

    if (lane < OUT_C) {
        float acc = 0.0f;
#pragma unroll
        for (int k = 0; k < HID; k++)
            acc = fmaf(sh[warp][k], sW[k * OUT_C + lane], acc);
        g_g2h[(size_t)node * OUT_C + lane] = __float2half(acc * dv);
    }
}

// K5: layer-2 scatter. 2 threads/edge; thread q: ONE uint4 fp16 gather
// (8 feats) -> ONE red.v4.f16x2 into parity bank e&3.
__global__ __launch_bounds__(256) void k_scat2() {
    int t = blockIdx.x * 256 + threadIdx.x;      // grid exact: E*2
    int e = t >> 1, q = t & 1;
    int r = g_row[e];
    int c = g_col[e];
    uint4 v = *(const uint4*)(g_g2h + (size_t)r * OUT_C + q * 8);
    __half* dst = g_acc2 + (size_t)(e & 3) * ACC2_BANK + (size_t)c * OUT_C + q * 8;
    red_f16x8(dst, v);
}

// K6: out = (sum of 4 banks)*dinv + b2; zero-fill tail (tuple scalar slot).
__global__ void k_final(float* __restrict__ out, const float* __restrict__ b2,
                        int out_size) {
    int t = blockIdx.x * blockDim.x + threadIdx.x;
    if (t >= out_size) return;
    if (t < N_NODES * OUT_C) {
        int c = t >> 4, j = t & 15;              // OUT_C == 16
        float a = (__half2float(g_acc2[t]) +
                   __half2float(g_acc2[ACC2_BANK + t])) +
                  (__half2float(g_acc2[2 * ACC2_BANK + t]) +
                   __half2float(g_acc2[3 * ACC2_BANK + t]));
        out[t] = a * g_dinv[c] + b2[j];
    } else {
        out[t] = 0.0f;
    }
}

// ---------------------------------------------------------------------------
extern "C" void kernel_launch(void* const* d_in, const int* in_sizes, int n_in,
                              void* d_out, int out_size) {
    const float* x  = (const float*)d_in[0];
    const void*  ei = d_in[1];
    const float* W1 = (const float*)d_in[2];
    const float* b1 = (const float*)d_in[3];
    const float* W2 = (const float*)d_in[4];
    const float* b2 = (const float*)d_in[5];
    float* out = (float*)d_out;

    void *p_degi, *p_acc1, *p_acc2;
    cudaGetSymbolAddress(&p_degi, g_degi);
    cudaGetSymbolAddress(&p_acc1, g_acc1);
    cudaGetSymbolAddress(&p_acc2, g_acc2);
    cudaMemsetAsync(p_degi, 0, (size_t)N_NODES * sizeof(int));
    cudaMemsetAsync(p_acc1, 0, 2 * ACC1_BANK * sizeof(__half));
    cudaMemsetAsync(p_acc2, 0, 4 * ACC2_BANK * sizeof(__half));

    k_fusedA<<<FA_BLOCKS, 256>>>(x, W1, ei);
    k_scale <<<(N_NODES * HID / 8 + 255) / 256, 256>>>();
    k_scat1 <<<(N_EDGES * 4) / 256, 256>>>();
    k_fuse  <<<(N_NODES + 7) / 8, 256>>>(W2, b1);
    k_scat2 <<<(N_EDGES * 2) / 256, 256>>>();
    k_final <<<(out_size + 255) / 256, 256>>>(out, b2, out_size);
}

// round 16
// speedup vs baseline: 2.5921x; 1.0561x over previous
#include <cuda_runtime.h>
#include <cuda_fp16.h>
#include <cstdint>

// ---------------------------------------------------------------------------
// GCNEncoder: 2-layer GCN, N=100000, E=3200000, 128 -> 32 -> 16.
//
// R15 = R14 (180.3us) + k_fuse redesign + vectorized k_final.
// R14 profile: k_fuse was 27.8us, issue-bound -- warp-per-node left 16/32
// lanes idle in the 32x16 GEMM. Now 2 nodes/warp: lanes 0-15 -> node A,
// lanes 16-31 -> node B; all lanes FMA every cycle; warp-instr/node halved.
// k_final: 8 outputs/thread (uint4 bank loads, float4 stores).
// Validated models (do not regress):
//  * scatter cost = RED lane count (16B wavefront/lane, payload-indep);
//    scat1 = 4 lanes/edge (floor), scat2 = 2 (floor).
//  * banked fp16 accumulators: error ~ 1/B, zero extra lanes.
//  * uniform-block GEMM+edge fusion in fusedA (R14).
// Sorted/CSR designs failed 4x. Do not revisit.
// ---------------------------------------------------------------------------

#define N_NODES 100000
#define N_EDGES 3200000
#define IN_C    128
#define HID     32
#define OUT_C   16

#define FA_BLOCKS (N_NODES / 32)       // 3125; also E/1024 = 3125 exactly

#define ACC1_BANK ((size_t)N_NODES * HID)
#define ACC2_BANK ((size_t)N_NODES * OUT_C)

// Scratch (no cudaMalloc allowed) ------------------------------------------
__device__ int    g_degi[N_NODES];
__device__ __align__(16) int g_row[N_EDGES];
__device__ __align__(16) int g_col[N_EDGES];
__device__ float  g_dinv[N_NODES];
__device__ __align__(16) float  g_g1 [N_NODES * HID];       // fp32 x@W1
__device__ __align__(16) __half g_g1h[N_NODES * HID];       // fp16 dinv*(x@W1)
__device__ __align__(16) __half g_acc1[2 * N_NODES * HID];  // 2 banks
__device__ __align__(16) __half g_g2h[N_NODES * OUT_C];     // fp16 dinv*(relu@W2)
__device__ __align__(16) __half g_acc2[4 * N_NODES * OUT_C];// 4 banks

__device__ __forceinline__ void red_f16x8(__half* dst, uint4 v) {
    asm volatile("red.global.add.noftz.v4.f16x2 [%0], {%1,%2,%3,%4};"
                 :: "l"(dst), "r"(v.x), "r"(v.y), "r"(v.z), "r"(v.w) : "memory");
}

// K1 (uniform fused): every block = [dtype detect] + [1024-edge decode +
// degree histogram] + [32-node register-tiled GEMM tile].
__global__ __launch_bounds__(256) void k_fusedA(const float* __restrict__ x,
                                                const float* __restrict__ W1,
                                                const void*  __restrict__ ei) {
    int tid = threadIdx.x;

    // ---- dtype detection: 256 int64 probes, block-uniform result ----
    long long probe = ((const long long*)ei)[tid];
    int is64 = !__syncthreads_or(probe < 0 || probe >= N_NODES);

    // ---- edge phase: 4 edges/thread, vectorized, fire-and-forget ----
    {
        int t = blockIdx.x * 256 + tid;           // quad index; e0 = 4t
        int4 rr, cc;
        if (is64) {
            longlong2 a = ((const longlong2*)ei)[t * 2];
            longlong2 b = ((const longlong2*)ei)[t * 2 + 1];
            longlong2 c = ((const longlong2*)ei)[N_EDGES / 2 + t * 2];
            longlong2 d = ((const longlong2*)ei)[N_EDGES / 2 + t * 2 + 1];
            rr = make_int4((int)a.x, (int)a.y, (int)b.x, (int)b.y);
            cc = make_int4((int)c.x, (int)c.y, (int)d.x, (int)d.y);
        } else {
            rr = ((const int4*)ei)[t];
            cc = ((const int4*)ei)[N_EDGES / 4 + t];
        }
        ((int4*)g_row)[t] = rr;
        ((int4*)g_col)[t] = cc;
        atomicAdd(&g_degi[cc.x], 1);
        atomicAdd(&g_degi[cc.y], 1);
        atomicAdd(&g_degi[cc.z], 1);
        atomicAdd(&g_degi[cc.w], 1);
    }

    // ---- GEMM phase: warp = 4 nodes x 32 features ----
    __shared__ float sW[IN_C * HID];
    __shared__ float sx[32][IN_C];
#pragma unroll
    for (int i = tid; i < (IN_C * HID) / 4; i += 256)
        ((float4*)sW)[i] = ((const float4*)W1)[i];

    int nb = blockIdx.x * 32;
#pragma unroll
    for (int i = tid; i < 32 * (IN_C / 4); i += 256) {
        int row = i >> 5, c4 = i & 31;
        ((float4*)sx[row])[c4] =
            ((const float4*)(x + (size_t)(nb + row) * IN_C))[c4];
    }
    __syncthreads();

    int warp = tid >> 5, lane = tid & 31;
    int n0 = warp * 4;
    float a0 = 0.f, a1 = 0.f, a2 = 0.f, a3 = 0.f;
#pragma unroll 4
    for (int kk = 0; kk < IN_C; kk += 4) {
        float4 xa = *(const float4*)&sx[n0 + 0][kk];
        float4 xb = *(const float4*)&sx[n0 + 1][kk];
        float4 xc = *(const float4*)&sx[n0 + 2][kk];
        float4 xd = *(const float4*)&sx[n0 + 3][kk];
        float w0 = sW[(kk + 0) * HID + lane];
        float w1 = sW[(kk + 1) * HID + lane];
        float w2 = sW[(kk + 2) * HID + lane];
        float w3 = sW[(kk + 3) * HID + lane];
        a0 = fmaf(xa.x, w0, fmaf(xa.y, w1, fmaf(xa.z, w2, fmaf(xa.w, w3, a0))));
        a1 = fmaf(xb.x, w0, fmaf(xb.y, w1, fmaf(xb.z, w2, fmaf(xb.w, w3, a1))));
        a2 = fmaf(xc.x, w0, fmaf(xc.y, w1, fmaf(xc.z, w2, fmaf(xc.w, w3, a2))));
        a3 = fmaf(xd.x, w0, fmaf(xd.y, w1, fmaf(xd.z, w2, fmaf(xd.w, w3, a3))));
    }
    g_g1[(size_t)(nb + n0 + 0) * HID + lane] = a0;
    g_g1[(size_t)(nb + n0 + 1) * HID + lane] = a1;
    g_g1[(size_t)(nb + n0 + 2) * HID + lane] = a2;
    g_g1[(size_t)(nb + n0 + 3) * HID + lane] = a3;
}

// K2: dinv = rsqrt(deg) (or 0); g1h = fp16(dinv * g1). 8 floats per thread.
__global__ void k_scale() {
    int i = blockIdx.x * blockDim.x + threadIdx.x;   // 8-float chunk index
    if (i >= N_NODES * HID / 8) return;
    int node = i >> 2;                               // 4 chunks per 32-f row
    int d = g_degi[node];
    float dv = (d > 0) ? rsqrtf((float)d) : 0.0f;
    const float4 a = ((const float4*)g_g1)[i * 2];
    const float4 b = ((const float4*)g_g1)[i * 2 + 1];
    uint4 o;
    *(__half2*)&o.x = __floats2half2_rn(a.x * dv, a.y * dv);
    *(__half2*)&o.y = __floats2half2_rn(a.z * dv, a.w * dv);
    *(__half2*)&o.z = __floats2half2_rn(b.x * dv, b.y * dv);
    *(__half2*)&o.w = __floats2half2_rn(b.z * dv, b.w * dv);
    ((uint4*)g_g1h)[i] = o;
    if ((i & 3) == 0) g_dinv[node] = dv;
}

// K3: layer-1 scatter. 4 threads/edge; thread q: ONE uint4 fp16 gather
// (8 feats) -> ONE red.v4.f16x2 into parity bank e&1.
__global__ __launch_bounds__(256) void k_scat1() {
    int t = blockIdx.x * 256 + threadIdx.x;      // grid exact: E*4
    int e = t >> 2, q = t & 3;
    int r = g_row[e];
    int c = g_col[e];
    uint4 v = *(const uint4*)(g_g1h + (size_t)r * HID + q * 8);
    __half* dst = g_acc1 + (size_t)(e & 1) * ACC1_BANK + (size_t)c * HID + q * 8;
    red_f16x8(dst, v);
}

// K4: 2 nodes per warp. h = relu((bank0+bank1)*dinv + b1);
// g2h = fp16(dinv*(h@W2)). Lanes 0-15 -> node A outputs, 16-31 -> node B.
__global__ __launch_bounds__(256) void k_fuse(const float* __restrict__ W2,
                                              const float* __restrict__ b1) {
    __shared__ float sW[HID * OUT_C];
    __shared__ float sb1[HID];
    __shared__ float sh[8][2 * HID];
    for (int i = threadIdx.x; i < HID * OUT_C; i += 256) sW[i] = W2[i];
    for (int i = threadIdx.x; i < HID; i += 256) sb1[i] = b1[i];
    __syncthreads();

    int warp = threadIdx.x >> 5, lane = threadIdx.x & 31;
    int na = blockIdx.x * 16 + warp * 2;         // grid = 6250, exact
    int nb = na + 1;

    // h phase: lane l computes feat l of both nodes (4 coalesced 64B runs).
    float dva = g_dinv[na], dvb = g_dinv[nb];
    size_t ia = (size_t)na * HID + lane, ib = (size_t)nb * HID + lane;
    float aa = __half2float(g_acc1[ia]) + __half2float(g_acc1[ACC1_BANK + ia]);
    float ab = __half2float(g_acc1[ib]) + __half2float(g_acc1[ACC1_BANK + ib]);
    sh[warp][lane]       = fmaxf(fmaf(aa, dva, sb1[lane]), 0.0f);
    sh[warp][HID + lane] = fmaxf(fmaf(ab, dvb, sb1[lane]), 0.0f);
    __syncwarp();

    // GEMM: all 32 lanes active. sel = node half, jj = output feature.
    int sel = lane >> 4, jj = lane & 15;
    const float* hrow = &sh[warp][sel * HID];
    float acc = 0.0f;
#pragma unroll
    for (int k = 0; k < HID; k++)
        acc = fmaf(hrow[k], sW[k * OUT_C + jj], acc);
    float dv = sel ? dvb : dva;
    int node = sel ? nb : na;
    g_g2h[(size_t)node * OUT_C + jj] = __float2half(acc * dv);
}

// K5: layer-2 scatter. 2 threads/edge; thread q: ONE uint4 fp16 gather
// (8 feats) -> ONE red.v4.f16x2 into parity bank e&3.
__global__ __launch_bounds__(256) void k_scat2() {
    int t = blockIdx.x * 256 + threadIdx.x;      // grid exact: E*2
    int e = t >> 1, q = t & 1;
    int r = g_row[e];
    int c = g_col[e];
    uint4 v = *(const uint4*)(g_g2h + (size_t)r * OUT_C + q * 8);
    __half* dst = g_acc2 + (size_t)(e & 3) * ACC2_BANK + (size_t)c * OUT_C + q * 8;
    red_f16x8(dst, v);
}

// K6: out = (sum of 4 banks)*dinv + b2, 8 outputs/thread (vectorized);
// then zero-fill tail (tuple scalar slot).
__global__ void k_final(float* __restrict__ out, const float* __restrict__ b2,
                        int out_size) {
    int i = blockIdx.x * blockDim.x + threadIdx.x;   // 8-elem chunk index
    int n8 = N_NODES * OUT_C / 8;                    // 200000
    if (i < n8) {
        int node = i >> 1, q = i & 1;                // half-row of 16
        size_t base = (size_t)i * 8;
        uint4 p0 = *(const uint4*)(g_acc2 + base);
        uint4 p1 = *(const uint4*)(g_acc2 + ACC1_BANK * 0 + ACC2_BANK + base);
        uint4 p2 = *(const uint4*)(g_acc2 + 2 * ACC2_BANK + base);
        uint4 p3 = *(const uint4*)(g_acc2 + 3 * ACC2_BANK + base);
        float dv = g_dinv[node];
        float4 oA, oB;
        {
            const __half2* h0 = (const __half2*)&p0;
            const __half2* h1 = (const __half2*)&p1;
            const __half2* h2 = (const __half2*)&p2;
            const __half2* h3 = (const __half2*)&p3;
            float r[8];
#pragma unroll
            for (int k = 0; k < 4; k++) {
                float2 f0 = __half22float2(h0[k]);
                float2 f1 = __half22float2(h1[k]);
                float2 f2 = __half22float2(h2[k]);
                float2 f3 = __half22float2(h3[k]);
                r[2 * k]     = (f0.x + f1.x) + (f2.x + f3.x);
                r[2 * k + 1] = (f0.y + f1.y) + (f2.y + f3.y);
            }
            int j0 = q * 8;
            oA = make_float4(r[0] * dv + b2[j0 + 0], r[1] * dv + b2[j0 + 1],
                             r[2] * dv + b2[j0 + 2], r[3] * dv + b2[j0 + 3]);
            oB = make_float4(r[4] * dv + b2[j0 + 4], r[5] * dv + b2[j0 + 5],
                             r[6] * dv + b2[j0 + 6], r[7] * dv + b2[j0 + 7]);
        }
        *(float4*)(out + base)     = oA;
        *(float4*)(out + base + 4) = oB;
    } else {
        // tail zero-fill
        int t = N_NODES * OUT_C + (i - n8);
        if (t < out_size) out[t] = 0.0f;
    }
}

// ---------------------------------------------------------------------------
extern "C" void kernel_launch(void* const* d_in, const int* in_sizes, int n_in,
                              void* d_out, int out_size) {
    const float* x  = (const float*)d_in[0];
    const void*  ei = d_in[1];
    const float* W1 = (const float*)d_in[2];
    const float* b1 = (const float*)d_in[3];
    const float* W2 = (const float*)d_in[4];
    const float* b2 = (const float*)d_in[5];
    float* out = (float*)d_out;

    void *p_degi, *p_acc1, *p_acc2;
    cudaGetSymbolAddress(&p_degi, g_degi);
    cudaGetSymbolAddress(&p_acc1, g_acc1);
    cudaGetSymbolAddress(&p_acc2, g_acc2);
    cudaMemsetAsync(p_degi, 0, (size_t)N_NODES * sizeof(int));
    cudaMemsetAsync(p_acc1, 0, 2 * ACC1_BANK * sizeof(__half));
    cudaMemsetAsync(p_acc2, 0, 4 * ACC2_BANK * sizeof(__half));

    k_fusedA<<<FA_BLOCKS, 256>>>(x, W1, ei);
    k_scale <<<(N_NODES * HID / 8 + 255) / 256, 256>>>();
    k_scat1 <<<(N_EDGES * 4) / 256, 256>>>();
    k_fuse  <<<N_NODES / 16, 256>>>(W2, b1);
    k_scat2 <<<(N_EDGES * 2) / 256, 256>>>();
    int fin_threads = N_NODES * OUT_C / 8 +
                      (out_size - N_NODES * OUT_C > 0 ? out_size - N_NODES * OUT_C : 0);
    k_final <<<(fin_threads + 255) / 256, 256>>>(out, b2, out_size);
}

// round 17
// speedup vs baseline: 2.6230x; 1.0120x over previous
#include <cuda_runtime.h>
#include <cuda_fp16.h>
#include <cstdint>

// ---------------------------------------------------------------------------
// GCNEncoder: 2-layer GCN, N=100000, E=3200000, 128 -> 32 -> 16.
//
// R16 = R15 (170.7us) + warp-specialized fusedA + register-W k_fuse.
//  * fusedA: R15's uniform blocks ran edge->GEMM phases in LOCKSTEP (sum,
//    not max). Now warps 0-3 = GEMM (16-node tile, named bar.sync 1,128),
//    warps 4-7 = edge decode+histogram (512 edges). True co-residency.
//  * k_fuse: lane caches its W2 column (32 regs); inner loop = broadcast
//    LDS + reg-FFMA. Warp does 4 nodes.
// Validated models (do not regress):
//  * scatter cost = RED lane count; scat1 = 4 lanes/edge (floor), scat2 = 2.
//  * banked fp16 accumulators: error ~ 1/B, zero extra lanes.
// Sorted/CSR designs failed 4x. Do not revisit.
// ---------------------------------------------------------------------------

#define N_NODES 100000
#define N_EDGES 3200000
#define IN_C    128
#define HID     32
#define OUT_C   16

#define FA_BLOCKS 6250                 // 16 nodes + 512 edges per block

#define ACC1_BANK ((size_t)N_NODES * HID)
#define ACC2_BANK ((size_t)N_NODES * OUT_C)

// Scratch (no cudaMalloc allowed) ------------------------------------------
__device__ int    g_degi[N_NODES];
__device__ __align__(16) int g_row[N_EDGES];
__device__ __align__(16) int g_col[N_EDGES];
__device__ float  g_dinv[N_NODES];
__device__ __align__(16) float  g_g1 [N_NODES * HID];       // fp32 x@W1
__device__ __align__(16) __half g_g1h[N_NODES * HID];       // fp16 dinv*(x@W1)
__device__ __align__(16) __half g_acc1[2 * N_NODES * HID];  // 2 banks
__device__ __align__(16) __half g_g2h[N_NODES * OUT_C];     // fp16 dinv*(relu@W2)
__device__ __align__(16) __half g_acc2[4 * N_NODES * OUT_C];// 4 banks

__device__ __forceinline__ void red_f16x8(__half* dst, uint4 v) {
    asm volatile("red.global.add.noftz.v4.f16x2 [%0], {%1,%2,%3,%4};"
                 :: "l"(dst), "r"(v.x), "r"(v.y), "r"(v.z), "r"(v.w) : "memory");
}

// K1 (warp-specialized): warps 0-3 = GEMM tile (16 nodes); warps 4-7 =
// edge decode (512 edges, 4/thread) + degree histogram. Dtype detect first
// (block-uniform, 256 int64 probes; misdetect prob ~(1e-5)^256 ~ 0).
__global__ __launch_bounds__(256) void k_fusedA(const float* __restrict__ x,
                                                const float* __restrict__ W1,
                                                const void*  __restrict__ ei) {
    int tid = threadIdx.x;

    long long probe = ((const long long*)ei)[tid];
    int is64 = !__syncthreads_or(probe < 0 || probe >= N_NODES);

    __shared__ float sW[IN_C * HID];    // 16KB
    __shared__ float sx[16][IN_C];      // 8KB

    if (tid >= 128) {
        // ---- edge warps: 4 edges/thread, fire-and-forget ----
        int t = blockIdx.x * 128 + (tid - 128);   // quad idx; 6250*128 = E/4
        int4 rr, cc;
        if (is64) {
            longlong2 a = ((const longlong2*)ei)[t * 2];
            longlong2 b = ((const longlong2*)ei)[t * 2 + 1];
            longlong2 c = ((const longlong2*)ei)[N_EDGES / 2 + t * 2];
            longlong2 d = ((const longlong2*)ei)[N_EDGES / 2 + t * 2 + 1];
            rr = make_int4((int)a.x, (int)a.y, (int)b.x, (int)b.y);
            cc = make_int4((int)c.x, (int)c.y, (int)d.x, (int)d.y);
        } else {
            rr = ((const int4*)ei)[t];
            cc = ((const int4*)ei)[N_EDGES / 4 + t];
        }
        ((int4*)g_row)[t] = rr;
        ((int4*)g_col)[t] = cc;
        atomicAdd(&g_degi[cc.x], 1);
        atomicAdd(&g_degi[cc.y], 1);
        atomicAdd(&g_degi[cc.z], 1);
        atomicAdd(&g_degi[cc.w], 1);
        return;
    }

    // ---- GEMM warps (0-3): fill smem with 128 threads, private barrier ----
#pragma unroll
    for (int i = tid; i < (IN_C * HID) / 4; i += 128)
        ((float4*)sW)[i] = ((const float4*)W1)[i];

    int nb = blockIdx.x * 16;
#pragma unroll
    for (int i = tid; i < 16 * (IN_C / 4); i += 128) {
        int row = i >> 5, c4 = i & 31;
        ((float4*)sx[row])[c4] =
            ((const float4*)(x + (size_t)(nb + row) * IN_C))[c4];
    }
    asm volatile("bar.sync 1, 128;" ::: "memory");

    int warp = tid >> 5, lane = tid & 31;
    int n0 = warp * 4;                  // rows 0..15 in sx
    float a0 = 0.f, a1 = 0.f, a2 = 0.f, a3 = 0.f;
#pragma unroll 4
    for (int kk = 0; kk < IN_C; kk += 4) {
        float4 xa = *(const float4*)&sx[n0 + 0][kk];
        float4 xb = *(const float4*)&sx[n0 + 1][kk];
        float4 xc = *(const float4*)&sx[n0 + 2][kk];
        float4 xd = *(const float4*)&sx[n0 + 3][kk];
        float w0 = sW[(kk + 0) * HID + lane];
        float w1 = sW[(kk + 1) * HID + lane];
        float w2 = sW[(kk + 2) * HID + lane];
        float w3 = sW[(kk + 3) * HID + lane];
        a0 = fmaf(xa.x, w0, fmaf(xa.y, w1, fmaf(xa.z, w2, fmaf(xa.w, w3, a0))));
        a1 = fmaf(xb.x, w0, fmaf(xb.y, w1, fmaf(xb.z, w2, fmaf(xb.w, w3, a1))));
        a2 = fmaf(xc.x, w0, fmaf(xc.y, w1, fmaf(xc.z, w2, fmaf(xc.w, w3, a2))));
        a3 = fmaf(xd.x, w0, fmaf(xd.y, w1, fmaf(xd.z, w2, fmaf(xd.w, w3, a3))));
    }
    g_g1[(size_t)(nb + n0 + 0) * HID + lane] = a0;
    g_g1[(size_t)(nb + n0 + 1) * HID + lane] = a1;
    g_g1[(size_t)(nb + n0 + 2) * HID + lane] = a2;
    g_g1[(size_t)(nb + n0 + 3) * HID + lane] = a3;
}

// K2: dinv = rsqrt(deg) (or 0); g1h = fp16(dinv * g1). 8 floats per thread.
__global__ void k_scale() {
    int i = blockIdx.x * blockDim.x + threadIdx.x;   // 8-float chunk index
    if (i >= N_NODES * HID / 8) return;
    int node = i >> 2;                               // 4 chunks per 32-f row
    int d = g_degi[node];
    float dv = (d > 0) ? rsqrtf((float)d) : 0.0f;
    const float4 a = ((const float4*)g_g1)[i * 2];
    const float4 b = ((const float4*)g_g1)[i * 2 + 1];
    uint4 o;
    *(__half2*)&o.x = __floats2half2_rn(a.x * dv, a.y * dv);
    *(__half2*)&o.y = __floats2half2_rn(a.z * dv, a.w * dv);
    *(__half2*)&o.z = __floats2half2_rn(b.x * dv, b.y * dv);
    *(__half2*)&o.w = __floats2half2_rn(b.z * dv, b.w * dv);
    ((uint4*)g_g1h)[i] = o;
    if ((i & 3) == 0) g_dinv[node] = dv;
}

// K3: layer-1 scatter. 4 threads/edge; thread q: ONE uint4 fp16 gather
// (8 feats) -> ONE red.v4.f16x2 into parity bank e&1.
__global__ __launch_bounds__(256) void k_scat1() {
    int t = blockIdx.x * 256 + threadIdx.x;      // grid exact: E*4
    int e = t >> 2, q = t & 3;
    int r = g_row[e];
    int c = g_col[e];
    uint4 v = *(const uint4*)(g_g1h + (size_t)r * HID + q * 8);
    __half* dst = g_acc1 + (size_t)(e & 1) * ACC1_BANK + (size_t)c * HID + q * 8;
    red_f16x8(dst, v);
}

// K4: warp = 4 nodes (2 pairs); lane caches its W2 column in 32 regs.
// h = relu((bank0+bank1)*dinv + b1); g2h = fp16(dinv*(h@W2)).
__global__ __launch_bounds__(256) void k_fuse(const float* __restrict__ W2,
                                              const float* __restrict__ b1) {
    __shared__ float sW[HID * OUT_C];
    __shared__ float sb1[HID];
    __shared__ float sh[8][2 * HID];
    for (int i = threadIdx.x; i < HID * OUT_C; i += 256) sW[i] = W2[i];
    if (threadIdx.x < HID) sb1[threadIdx.x] = b1[threadIdx.x];
    __syncthreads();

    int warp = threadIdx.x >> 5, lane = threadIdx.x & 31;
    int jj = lane & 15, sel = lane >> 4;
    float wcol[HID];
#pragma unroll
    for (int k = 0; k < HID; k++) wcol[k] = sW[k * OUT_C + jj];
    float bl = sb1[lane];

    int base = blockIdx.x * 32 + warp * 4;       // grid = 3125, exact
#pragma unroll
    for (int p = 0; p < 2; p++) {
        int na = base + 2 * p, nb = na + 1;
        float dva = g_dinv[na], dvb = g_dinv[nb];
        size_t ia = (size_t)na * HID + lane, ib = ia + HID;
        float aa = __half2float(g_acc1[ia]) + __half2float(g_acc1[ACC1_BANK + ia]);
        float ab = __half2float(g_acc1[ib]) + __half2float(g_acc1[ACC1_BANK + ib]);
        sh[warp][lane]       = fmaxf(fmaf(aa, dva, bl), 0.0f);
        sh[warp][HID + lane] = fmaxf(fmaf(ab, dvb, bl), 0.0f);
        __syncwarp();

        const float* hrow = &sh[warp][sel * HID];
        float acc = 0.0f;
#pragma unroll
        for (int k = 0; k < HID; k++)
            acc = fmaf(hrow[k], wcol[k], acc);
        float dv = sel ? dvb : dva;
        int node = sel ? nb : na;
        g_g2h[(size_t)node * OUT_C + jj] = __float2half(acc * dv);
        __syncwarp();
    }
}

// K5: layer-2 scatter. 2 threads/edge; thread q: ONE uint4 fp16 gather
// (8 feats) -> ONE red.v4.f16x2 into parity bank e&3.
__global__ __launch_bounds__(256) void k_scat2() {
    int t = blockIdx.x * 256 + threadIdx.x;      // grid exact: E*2
    int e = t >> 1, q = t & 1;
    int r = g_row[e];
    int c = g_col[e];
    uint4 v = *(const uint4*)(g_g2h + (size_t)r * OUT_C + q * 8);
    __half* dst = g_acc2 + (size_t)(e & 3) * ACC2_BANK + (size_t)c * OUT_C + q * 8;
    red_f16x8(dst, v);
}

// K6: out = (sum of 4 banks)*dinv + b2, 8 outputs/thread; zero tail.
__global__ void k_final(float* __restrict__ out, const float* __restrict__ b2,
                        int out_size) {
    int i = blockIdx.x * blockDim.x + threadIdx.x;   // 8-elem chunk index
    int n8 = N_NODES * OUT_C / 8;                    // 200000
    if (i < n8) {
        int node = i >> 1, q = i & 1;
        size_t base = (size_t)i * 8;
        uint4 p0 = *(const uint4*)(g_acc2 + base);
        uint4 p1 = *(const uint4*)(g_acc2 + ACC2_BANK + base);
        uint4 p2 = *(const uint4*)(g_acc2 + 2 * ACC2_BANK + base);
        uint4 p3 = *(const uint4*)(g_acc2 + 3 * ACC2_BANK + base);
        float dv = g_dinv[node];
        const __half2* h0 = (const __half2*)&p0;
        const __half2* h1 = (const __half2*)&p1;
        const __half2* h2 = (const __half2*)&p2;
        const __half2* h3 = (const __half2*)&p3;
        float r[8];
#pragma unroll
        for (int k = 0; k < 4; k++) {
            float2 f0 = __half22float2(h0[k]);
            float2 f1 = __half22float2(h1[k]);
            float2 f2 = __half22float2(h2[k]);
            float2 f3 = __half22float2(h3[k]);
            r[2 * k]     = (f0.x + f1.x) + (f2.x + f3.x);
            r[2 * k + 1] = (f0.y + f1.y) + (f2.y + f3.y);
        }
        int j0 = q * 8;
        float4 oA = make_float4(r[0] * dv + b2[j0 + 0], r[1] * dv + b2[j0 + 1],
                                r[2] * dv + b2[j0 + 2], r[3] * dv + b2[j0 + 3]);
        float4 oB = make_float4(r[4] * dv + b2[j0 + 4], r[5] * dv + b2[j0 + 5],
                                r[6] * dv + b2[j0 + 6], r[7] * dv + b2[j0 + 7]);
        *(float4*)(out + base)     = oA;
        *(float4*)(out + base + 4) = oB;
    } else {
        int t = N_NODES * OUT_C + (i - n8);
        if (t < out_size) out[t] = 0.0f;
    }
}

// ---------------------------------------------------------------------------
extern "C" void kernel_launch(void* const* d_in, const int* in_sizes, int n_in,
                              void* d_out, int out_size) {
    const float* x  = (const float*)d_in[0];
    const void*  ei = d_in[1];
    const float* W1 = (const float*)d_in[2];
    const float* b1 = (const float*)d_in[3];
    const float* W2 = (const float*)d_in[4];
    const float* b2 = (const float*)d_in[5];
    float* out = (float*)d_out;

    void *p_degi, *p_acc1, *p_acc2;
    cudaGetSymbolAddress(&p_degi, g_degi);
    cudaGetSymbolAddress(&p_acc1, g_acc1);
    cudaGetSymbolAddress(&p_acc2, g_acc2);
    cudaMemsetAsync(p_degi, 0, (size_t)N_NODES * sizeof(int));
    cudaMemsetAsync(p_acc1, 0, 2 * ACC1_BANK * sizeof(__half));
    cudaMemsetAsync(p_acc2, 0, 4 * ACC2_BANK * sizeof(__half));

    k_fusedA<<<FA_BLOCKS, 256>>>(x, W1, ei);
    k_scale <<<(N_NODES * HID / 8 + 255) / 256, 256>>>();
    k_scat1 <<<(N_EDGES * 4) / 256, 256>>>();
    k_fuse  <<<N_NODES / 32, 256>>>(W2, b1);
    k_scat2 <<<(N_EDGES * 2) / 256, 256>>>();
    int fin_threads = N_NODES * OUT_C / 8 +
                      (out_size - N_NODES * OUT_C > 0 ? out_size - N_NODES * OUT_C : 0);
    k_final <<<(fin_threads + 255) / 256, 256>>>(out, b2, out_size);
}